// round 10
// baseline (speedup 1.0000x reference)
#include <cuda_runtime.h>
#include <cstdint>

// ---------------------------------------------------------------------------
// NodeBernNet fixed shapes: N=100000, E=1600000, C_IN=128, C=64, F=2, K+1=4.
// R10: csr-prefetch pipelined spmm; xproj GEMM overlapped on forked stream;
// slimmer mega_tail (reads precomputed xproj).
// ---------------------------------------------------------------------------

#define NMAX 100000
#define EMAX 1600000
#define CDIM 64

__device__ __align__(256) float g_h   [NMAX * CDIM];
__device__ __align__(256) float g_T1  [NMAX * CDIM];
__device__ __align__(256) float g_T2  [NMAX * CDIM];
__device__ __align__(256) float g_xp  [NMAX * CDIM];
// CSR scratch
__device__ int g_cnt[NMAX];                 // count adds, scatter subtracts -> 0
__device__ int g_off[NMAX + 1];
__device__ unsigned long long g_pack[128];  // lookback {flag<<32 | aggregate}
__device__ __align__(16) int2 g_csr[EMAX];  // {src, val bits}

__device__ float g_coef[8];   // thetas @ BCOEF, [F=2][K+1=4]
__device__ int   g_is64;

// ---------------------------------------------------------------------------
__global__ void prep_kernel(const void* __restrict__ esrc,
                            const float* __restrict__ thetas)
{
    if (threadIdx.x == 0) {
        const int* w = (const int*)esrc;
        g_is64 = (w[1] == 0 && w[3] == 0 && w[5] == 0 && w[7] == 0) ? 1 : 0;
        const float B[4][4] = {
            {1.f, -3.f,  3.f, -1.f},
            {0.f,  3.f, -6.f,  3.f},
            {0.f,  0.f,  3.f, -3.f},
            {0.f,  0.f,  0.f,  1.f}};
        for (int f = 0; f < 2; f++)
            for (int k = 0; k < 4; k++) {
                float s = 0.f;
                for (int j = 0; j < 4; j++) s += thetas[f * 4 + j] * B[j][k];
                g_coef[f * 4 + k] = s;
            }
    }
}

// ---------------------------------------------------------------------------
// GEMM body: C = act(A[M,K] @ W[K,64] + bias), 128-row tile at m0. K=128|64.
// ---------------------------------------------------------------------------
__device__ __forceinline__ void gemm_body(const float* __restrict__ A,
                                          const float* __restrict__ W,
                                          const float* __restrict__ bias,
                                          float* __restrict__ C,
                                          int M, int K, int m0, int act)
{
    __shared__ float As[16][132];
    __shared__ float Bs[16][68];

    const int tid = threadIdx.x;
    const int tx = tid & 15;
    const int ty = tid >> 4;

    float acc[8][4] = {};

    for (int k0 = 0; k0 < K; k0 += 16) {
        #pragma unroll
        for (int r = 0; r < 2; r++) {
            int i = tid + r * 256;
            int row = i >> 2, kq = i & 3;
            int gm = m0 + row;
            float4 v = make_float4(0.f, 0.f, 0.f, 0.f);
            if (gm < M) v = *(const float4*)(A + (size_t)gm * K + k0 + kq * 4);
            As[kq * 4 + 0][row] = v.x;
            As[kq * 4 + 1][row] = v.y;
            As[kq * 4 + 2][row] = v.z;
            As[kq * 4 + 3][row] = v.w;
        }
        {
            int k = tid >> 4, nn = (tid & 15) * 4;
            float4 v = *(const float4*)(W + (size_t)(k0 + k) * 64 + nn);
            Bs[k][nn + 0] = v.x; Bs[k][nn + 1] = v.y;
            Bs[k][nn + 2] = v.z; Bs[k][nn + 3] = v.w;
        }
        __syncthreads();
        #pragma unroll
        for (int kk = 0; kk < 16; kk++) {
            float4 a0 = *(const float4*)&As[kk][ty * 8];
            float4 a1 = *(const float4*)&As[kk][ty * 8 + 4];
            float4 b  = *(const float4*)&Bs[kk][tx * 4];
            float am[8] = {a0.x, a0.y, a0.z, a0.w, a1.x, a1.y, a1.z, a1.w};
            float bn[4] = {b.x, b.y, b.z, b.w};
            #pragma unroll
            for (int i = 0; i < 8; i++)
                #pragma unroll
                for (int j = 0; j < 4; j++)
                    acc[i][j] += am[i] * bn[j];
        }
        __syncthreads();
    }

    int nn = tx * 4;
    float4 bv = *(const float4*)(bias + nn);
    #pragma unroll
    for (int i = 0; i < 8; i++) {
        int gm = m0 + ty * 8 + i;
        if (gm >= M) continue;
        float4 o;
        o.x = acc[i][0] + bv.x;
        o.y = acc[i][1] + bv.y;
        o.z = acc[i][2] + bv.z;
        o.w = acc[i][3] + bv.w;
        if (act) {
            o.x = fmaxf(o.x, 0.f); o.y = fmaxf(o.y, 0.f);
            o.z = fmaxf(o.z, 0.f); o.w = fmaxf(o.w, 0.f);
        }
        *(float4*)(C + (size_t)gm * 64 + nn) = o;
    }
}

// ---------------------------------------------------------------------------
// fat1: blocks [0,GA) gemm rows [0,GA*128); blocks [GA,..) count histogram.
// ---------------------------------------------------------------------------
__global__ void fat1(const float* __restrict__ A,
                     const float* __restrict__ W,
                     const float* __restrict__ bias,
                     float* __restrict__ C, int M,
                     const void* __restrict__ edst, int E, int GA)
{
    if ((int)blockIdx.x >= GA) {
        if ((int)blockIdx.x == GA && threadIdx.x < 128)
            g_pack[threadIdx.x] = 0ULL;
        int e = (blockIdx.x - GA) * blockDim.x + threadIdx.x;
        if (e < E) {
            int dst = g_is64 ? (int)((const long long*)edst)[e]
                             : ((const int*)edst)[e];
            atomicAdd(&g_cnt[dst], 1);
        }
        return;
    }
    gemm_body(A, W, bias, C, M, 128, blockIdx.x * 128, 1);
}

// ---------------------------------------------------------------------------
// Single-pass scan with decoupled lookback.
// ---------------------------------------------------------------------------
__global__ void scan_kernel(int n)
{
    __shared__ int warp_sums[32];
    __shared__ int s_prefix;

    int t = threadIdx.x, bid = blockIdx.x;
    int i = bid * 1024 + t;
    int lane = t & 31, wid = t >> 5;

    int x = (i < n) ? g_cnt[i] : 0;
    #pragma unroll
    for (int o = 1; o < 32; o <<= 1) {
        int y = __shfl_up_sync(0xffffffffu, x, o);
        if (lane >= o) x += y;
    }
    if (lane == 31) warp_sums[wid] = x;
    __syncthreads();
    if (wid == 0) {
        int s = warp_sums[lane];
        #pragma unroll
        for (int o = 1; o < 32; o <<= 1) {
            int y = __shfl_up_sync(0xffffffffu, s, o);
            if (lane >= o) s += y;
        }
        warp_sums[lane] = s;
    }
    __syncthreads();
    int incl = x + (wid > 0 ? warp_sums[wid - 1] : 0);
    int aggregate = warp_sums[31];

    if (t == 0) {
        if (bid == 0) {
            *(volatile unsigned long long*)&g_pack[0] =
                (2ULL << 32) | (unsigned)aggregate;
            s_prefix = 0;
        } else {
            *(volatile unsigned long long*)&g_pack[bid] =
                (1ULL << 32) | (unsigned)aggregate;
            int sum = 0;
            for (int j = bid - 1; j >= 0; j--) {
                unsigned long long p;
                do { p = *(volatile unsigned long long*)&g_pack[j]; }
                while ((p >> 32) == 0ULL);
                sum += (int)(unsigned)p;
                if ((p >> 32) == 2ULL) break;
            }
            *(volatile unsigned long long*)&g_pack[bid] =
                (2ULL << 32) | (unsigned)(sum + aggregate);
            s_prefix = sum;
        }
    }
    __syncthreads();
    if (i < n) g_off[i + 1] = s_prefix + incl;
    if (i == 0) g_off[0] = 0;
}

// ---------------------------------------------------------------------------
// fat2: blocks [0,GB) gemm rows from GA*128; rest scatter (self-zeroing cnt).
// ---------------------------------------------------------------------------
__global__ void fat2(const float* __restrict__ A,
                     const float* __restrict__ W,
                     const float* __restrict__ bias,
                     float* __restrict__ C, int M,
                     const void* __restrict__ esrc,
                     const void* __restrict__ edst,
                     const float* __restrict__ ev,
                     int E, int GA, int GB)
{
    if ((int)blockIdx.x >= GB) {
        int e = (blockIdx.x - GB) * 256 + threadIdx.x;
        if (e < E) {
            int src, dst;
            if (g_is64) {
                src = (int)((const long long*)esrc)[e];
                dst = (int)((const long long*)edst)[e];
            } else {
                src = ((const int*)esrc)[e];
                dst = ((const int*)edst)[e];
            }
            int old = atomicSub(&g_cnt[dst], 1);   // old in [1, cnt]
            g_csr[g_off[dst + 1] - old] = make_int2(src, __float_as_int(ev[e]));
        }
        return;
    }
    gemm_body(A, W, bias, C, M, 128, (GA + blockIdx.x) * 128, 1);
}

// ---------------------------------------------------------------------------
// xproj GEMM (runs on forked stream, overlapped with spmm hops).
// ---------------------------------------------------------------------------
__global__ void gemm64(const float* __restrict__ A,
                       const float* __restrict__ W,
                       const float* __restrict__ bias,
                       float* __restrict__ C, int M)
{
    gemm_body(A, W, bias, C, M, 64, blockIdx.x * 128, 0);
}

// ---------------------------------------------------------------------------
// CSR row gather-accumulate: float4 per 16-lane half, software-pipelined
// csr prefetch (batch k+1 loads issue before batch k's gathers complete).
// ---------------------------------------------------------------------------
__device__ __forceinline__ float4 spmm_row_acc(const float* __restrict__ hin,
                                               int s, int e, int lane16)
{
    float4 acc = make_float4(0.f, 0.f, 0.f, 0.f);
    int nb = (e - s) >> 2;
    int i = s;
    if (nb > 0) {
        int2 c0 = __ldg(&g_csr[i]);
        int2 c1 = __ldg(&g_csr[i + 1]);
        int2 c2 = __ldg(&g_csr[i + 2]);
        int2 c3 = __ldg(&g_csr[i + 3]);
        for (int b = 1; b < nb; b++) {
            int j = s + b * 4;
            int2 n0 = __ldg(&g_csr[j]);
            int2 n1 = __ldg(&g_csr[j + 1]);
            int2 n2 = __ldg(&g_csr[j + 2]);
            int2 n3 = __ldg(&g_csr[j + 3]);
            float4 h0 = *((const float4*)(hin + (size_t)c0.x * CDIM) + lane16);
            float4 h1 = *((const float4*)(hin + (size_t)c1.x * CDIM) + lane16);
            float4 h2 = *((const float4*)(hin + (size_t)c2.x * CDIM) + lane16);
            float4 h3 = *((const float4*)(hin + (size_t)c3.x * CDIM) + lane16);
            float v0 = __int_as_float(c0.y), v1 = __int_as_float(c1.y);
            float v2 = __int_as_float(c2.y), v3 = __int_as_float(c3.y);
            acc.x += v0 * h0.x + v1 * h1.x + v2 * h2.x + v3 * h3.x;
            acc.y += v0 * h0.y + v1 * h1.y + v2 * h2.y + v3 * h3.y;
            acc.z += v0 * h0.z + v1 * h1.z + v2 * h2.z + v3 * h3.z;
            acc.w += v0 * h0.w + v1 * h1.w + v2 * h2.w + v3 * h3.w;
            c0 = n0; c1 = n1; c2 = n2; c3 = n3;
        }
        {
            float4 h0 = *((const float4*)(hin + (size_t)c0.x * CDIM) + lane16);
            float4 h1 = *((const float4*)(hin + (size_t)c1.x * CDIM) + lane16);
            float4 h2 = *((const float4*)(hin + (size_t)c2.x * CDIM) + lane16);
            float4 h3 = *((const float4*)(hin + (size_t)c3.x * CDIM) + lane16);
            float v0 = __int_as_float(c0.y), v1 = __int_as_float(c1.y);
            float v2 = __int_as_float(c2.y), v3 = __int_as_float(c3.y);
            acc.x += v0 * h0.x + v1 * h1.x + v2 * h2.x + v3 * h3.x;
            acc.y += v0 * h0.y + v1 * h1.y + v2 * h2.y + v3 * h3.y;
            acc.z += v0 * h0.z + v1 * h1.z + v2 * h2.z + v3 * h3.z;
            acc.w += v0 * h0.w + v1 * h1.w + v2 * h2.w + v3 * h3.w;
        }
        i = s + nb * 4;
    }
    for (; i < e; i++) {
        int2 p0 = __ldg(&g_csr[i]);
        float v0 = __int_as_float(p0.y);
        float4 h0 = *((const float4*)(hin + (size_t)p0.x * CDIM) + lane16);
        acc.x += v0 * h0.x; acc.y += v0 * h0.y;
        acc.z += v0 * h0.z; acc.w += v0 * h0.w;
    }
    return acc;
}

__global__ void spmm_csr(const float* __restrict__ hin,
                         float* __restrict__ hout, int n)
{
    int w = (blockIdx.x * blockDim.x + threadIdx.x) >> 5;
    int lane = threadIdx.x & 31;
    int r = w * 2 + (lane >> 4);
    if (r >= n) return;
    int lane16 = lane & 15;
    float4 acc = spmm_row_acc(hin, g_off[r], g_off[r + 1], lane16);
    *((float4*)(hout + (size_t)r * CDIM) + lane16) = acc;
}

// ---------------------------------------------------------------------------
// Mega-tail (slim): hop-3 gather + poly -> Ps; score (xproj precomputed);
// softmax; res; 3-layer MLP head. 64 nodes per 256-thread block.
// ---------------------------------------------------------------------------
#define TAIL_SMEM_FLOATS (64*68 + 64*68 + 64*137 + 128 + 64 + 64)

__global__ void mega_tail(const float* __restrict__ h,
                          const float* __restrict__ t1,
                          const float* __restrict__ t2,
                          const float* __restrict__ xproj,
                          const float* __restrict__ Wb,
                          const float* __restrict__ bWb,
                          const float* __restrict__ vc,
                          const float* __restrict__ W1,
                          const float* __restrict__ b1,
                          const float* __restrict__ W2,
                          const float* __restrict__ b2,
                          const float* __restrict__ W3,
                          const float* __restrict__ b3,
                          float* __restrict__ out, int nn)
{
    extern __shared__ float sm[];
    float* As  = sm;                 // [k][m] 64x68 (res stage onward)
    float* Ws  = As + 64 * 68;       // [k][n] 64x68
    float* Ps  = Ws + 64 * 68;       // [c][row] 64x137 (poly, 128 rows)
    float* Ss  = Ps + 64 * 137;      // 128 scores
    float* Sa0 = Ss + 128;
    float* Sa1 = Sa0 + 64;

    const int tid = threadIdx.x;
    const int b0 = blockIdx.x * 64;
    const int tx = tid & 15;
    const int ty = tid >> 4;

    // ---- Wb -> Ws (independent of stage A; single sync covers both) ----
    #pragma unroll
    for (int r = 0; r < 4; r++) {
        int i = tid + r * 256;
        int k = i >> 4, nq = (i & 15) * 4;
        float4 v = *(const float4*)(Wb + (size_t)k * 64 + nq);
        Ws[k * 68 + nq]     = v.x; Ws[k * 68 + nq + 1] = v.y;
        Ws[k * 68 + nq + 2] = v.z; Ws[k * 68 + nq + 3] = v.w;
    }

    // ---- stage A: hop-3 gather + poly, 2 rows per warp -> Ps ----
    {
        int wid = tid >> 5;
        int lane = tid & 31;
        int lane16 = lane & 15;
        float c00 = g_coef[0], c01 = g_coef[1], c02 = g_coef[2], c03 = g_coef[3];
        float c10 = g_coef[4], c11 = g_coef[5], c12 = g_coef[6], c13 = g_coef[7];
        #pragma unroll
        for (int it = 0; it < 4; it++) {
            int local = wid * 8 + it * 2 + (lane >> 4);
            int r = b0 + local;
            float4 p0 = make_float4(0.f, 0.f, 0.f, 0.f);
            float4 p1 = make_float4(0.f, 0.f, 0.f, 0.f);
            if (r < nn) {
                float4 d = spmm_row_acc(t2, g_off[r], g_off[r + 1], lane16);
                float4 a = *((const float4*)(h  + (size_t)r * CDIM) + lane16);
                float4 b = *((const float4*)(t1 + (size_t)r * CDIM) + lane16);
                float4 c = *((const float4*)(t2 + (size_t)r * CDIM) + lane16);
                p0.x = c00*a.x + c01*b.x + c02*c.x + c03*d.x;
                p0.y = c00*a.y + c01*b.y + c02*c.y + c03*d.y;
                p0.z = c00*a.z + c01*b.z + c02*c.z + c03*d.z;
                p0.w = c00*a.w + c01*b.w + c02*c.w + c03*d.w;
                p1.x = c10*a.x + c11*b.x + c12*c.x + c13*d.x;
                p1.y = c10*a.y + c11*b.y + c12*c.y + c13*d.y;
                p1.z = c10*a.z + c11*b.z + c12*c.z + c13*d.z;
                p1.w = c10*a.w + c11*b.w + c12*c.w + c13*d.w;
            }
            int cb = lane16 * 4;
            int m2 = 2 * local;
            Ps[(cb + 0) * 137 + m2] = p0.x; Ps[(cb + 0) * 137 + m2 + 1] = p1.x;
            Ps[(cb + 1) * 137 + m2] = p0.y; Ps[(cb + 1) * 137 + m2 + 1] = p1.y;
            Ps[(cb + 2) * 137 + m2] = p0.z; Ps[(cb + 2) * 137 + m2 + 1] = p1.z;
            Ps[(cb + 3) * 137 + m2] = p0.w; Ps[(cb + 3) * 137 + m2 + 1] = p1.w;
        }
    }

    // ---- xp registers from precomputed xproj ----
    float xp[4][4];
    #pragma unroll
    for (int i = 0; i < 4; i++) {
        int gm = b0 + ty * 4 + i;
        float4 v = make_float4(0.f, 0.f, 0.f, 0.f);
        if (gm < nn) v = *(const float4*)(xproj + (size_t)gm * 64 + tx * 4);
        xp[i][0] = v.x; xp[i][1] = v.y; xp[i][2] = v.z; xp[i][3] = v.w;
    }
    __syncthreads();

    // ---- stage 2: scores ----
    {
        float acc2[8][4] = {};
        #pragma unroll
        for (int kk = 0; kk < 64; kk++) {
            float4 b = *(const float4*)&Ws[kk * 68 + tx * 4];
            float bn[4] = {b.x, b.y, b.z, b.w};
            const float* pr = &Ps[kk * 137 + ty * 8];
            #pragma unroll
            for (int i = 0; i < 8; i++) {
                float av = pr[i];
                acc2[i][0] += av * bn[0];
                acc2[i][1] += av * bn[1];
                acc2[i][2] += av * bn[2];
                acc2[i][3] += av * bn[3];
            }
        }
        float4 bb = *(const float4*)(bWb + tx * 4);
        float4 vv = *(const float4*)(vc + tx * 4);
        #pragma unroll
        for (int i = 0; i < 8; i++) {
            int h2 = i >> 1;
            float part;
            part  = tanhf(acc2[i][0] + bb.x + xp[h2][0]) * vv.x;
            part += tanhf(acc2[i][1] + bb.y + xp[h2][1]) * vv.y;
            part += tanhf(acc2[i][2] + bb.z + xp[h2][2]) * vv.z;
            part += tanhf(acc2[i][3] + bb.w + xp[h2][3]) * vv.w;
            #pragma unroll
            for (int o = 8; o > 0; o >>= 1)
                part += __shfl_xor_sync(0xffffffffu, part, o);
            if (tx == 0) Ss[ty * 8 + i] = part;
        }
    }
    __syncthreads();

    // ---- softmax per node ----
    if (tid < 64) {
        float s0 = Ss[2 * tid], s1 = Ss[2 * tid + 1];
        float m = fmaxf(s0, s1);
        float e0 = expf(s0 - m), e1 = expf(s1 - m);
        float inv = 1.f / (e0 + e1);
        Sa0[tid] = e0 * inv;
        Sa1[tid] = e1 * inv;
    }
    __syncthreads();

    // ---- res -> As, W1 -> Ws ----
    #pragma unroll
    for (int r = 0; r < 16; r++) {
        int i = tid + r * 256;
        int c = i >> 6, m = i & 63;
        As[c * 68 + m] = Sa0[m] * Ps[c * 137 + 2 * m]
                       + Sa1[m] * Ps[c * 137 + 2 * m + 1];
    }
    #pragma unroll
    for (int r = 0; r < 4; r++) {
        int i = tid + r * 256;
        int k = i >> 4, nq = (i & 15) * 4;
        float4 v = *(const float4*)(W1 + (size_t)k * 64 + nq);
        Ws[k * 68 + nq]     = v.x; Ws[k * 68 + nq + 1] = v.y;
        Ws[k * 68 + nq + 2] = v.z; Ws[k * 68 + nq + 3] = v.w;
    }
    __syncthreads();

    // ---- y1 = relu(res @ W1 + b1) ----
    float acc[4][4] = {};
    #pragma unroll
    for (int kk = 0; kk < 64; kk++) {
        float4 a = *(const float4*)&As[kk * 68 + ty * 4];
        float4 b = *(const float4*)&Ws[kk * 68 + tx * 4];
        float am[4] = {a.x, a.y, a.z, a.w};
        float bn[4] = {b.x, b.y, b.z, b.w};
        #pragma unroll
        for (int i = 0; i < 4; i++)
            #pragma unroll
            for (int j = 0; j < 4; j++)
                acc[i][j] += am[i] * bn[j];
    }
    __syncthreads();

    {
        float4 bv = *(const float4*)(b1 + tx * 4);
        float bbv[4] = {bv.x, bv.y, bv.z, bv.w};
        #pragma unroll
        for (int i = 0; i < 4; i++)
            #pragma unroll
            for (int j = 0; j < 4; j++)
                As[(tx * 4 + j) * 68 + ty * 4 + i] = fmaxf(acc[i][j] + bbv[j], 0.f);
    }
    #pragma unroll
    for (int r = 0; r < 2; r++) {
        int i = tid + r * 256;
        int k = i >> 3, nq = (i & 7) * 4;
        float4 v = *(const float4*)(W2 + (size_t)k * 32 + nq);
        Ws[k * 68 + nq]     = v.x; Ws[k * 68 + nq + 1] = v.y;
        Ws[k * 68 + nq + 2] = v.z; Ws[k * 68 + nq + 3] = v.w;
    }
    __syncthreads();

    // ---- y2 = relu(y1@W2+b2); out = y2@W3+b3 ----
    const int tx2 = tid & 15;
    const int ty2 = tid >> 4;
    float acc3[4][2] = {};
    #pragma unroll
    for (int kk = 0; kk < 64; kk++) {
        float4 a = *(const float4*)&As[kk * 68 + ty2 * 4];
        float b0v = Ws[kk * 68 + tx2 * 2];
        float b1v = Ws[kk * 68 + tx2 * 2 + 1];
        float am[4] = {a.x, a.y, a.z, a.w};
        #pragma unroll
        for (int i = 0; i < 4; i++) {
            acc3[i][0] += am[i] * b0v;
            acc3[i][1] += am[i] * b1v;
        }
    }
    float bb0 = b2[tx2 * 2], bb1 = b2[tx2 * 2 + 1];
    float w00 = W3[(tx2 * 2) * 2],     w01 = W3[(tx2 * 2) * 2 + 1];
    float w10 = W3[(tx2 * 2 + 1) * 2], w11 = W3[(tx2 * 2 + 1) * 2 + 1];

    #pragma unroll
    for (int i = 0; i < 4; i++) {
        float y0 = fmaxf(acc3[i][0] + bb0, 0.f);
        float y1v = fmaxf(acc3[i][1] + bb1, 0.f);
        float s0 = y0 * w00 + y1v * w10;
        float s1 = y0 * w01 + y1v * w11;
        #pragma unroll
        for (int o = 8; o > 0; o >>= 1) {
            s0 += __shfl_xor_sync(0xffffffffu, s0, o);
            s1 += __shfl_xor_sync(0xffffffffu, s1, o);
        }
        int gm = b0 + ty2 * 4 + i;
        if (tx2 == 0 && gm < nn) {
            out[gm * 2]     = s0 + b3[0];
            out[gm * 2 + 1] = s1 + b3[1];
        }
    }
}

// ---------------------------------------------------------------------------
extern "C" void kernel_launch(void* const* d_in, const int* in_sizes, int n_in,
                              void* d_out, int out_size)
{
    const float* x      = (const float*)d_in[0];
    const void*  esrc   = d_in[1];
    const void*  edst   = d_in[2];
    const float* ev     = (const float*)d_in[3];
    const float* Win    = (const float*)d_in[4];
    const float* bin    = (const float*)d_in[5];
    const float* thetas = (const float*)d_in[6];
    const float* Wb     = (const float*)d_in[7];
    const float* bWb    = (const float*)d_in[8];
    const float* Wx     = (const float*)d_in[9];
    const float* bWx    = (const float*)d_in[10];
    const float* vc     = (const float*)d_in[11];
    const float* W1     = (const float*)d_in[12];
    const float* b1     = (const float*)d_in[13];
    const float* W2     = (const float*)d_in[14];
    const float* b2     = (const float*)d_in[15];
    const float* W3     = (const float*)d_in[16];
    const float* b3     = (const float*)d_in[17];

    int n = in_sizes[0] / 128;
    int E = in_sizes[3];

    float *ph, *pT1, *pT2, *pxp;
    cudaGetSymbolAddress((void**)&ph,  g_h);
    cudaGetSymbolAddress((void**)&pT1, g_T1);
    cudaGetSymbolAddress((void**)&pT2, g_T2);
    cudaGetSymbolAddress((void**)&pxp, g_xp);

    // One-time host-side setup (created on the uncaptured correctness call).
    static cudaStream_t s2 = nullptr;
    static cudaEvent_t evH = nullptr, evX = nullptr;
    static int smem_set = 0;
    const int tail_smem = TAIL_SMEM_FLOATS * (int)sizeof(float);
    if (!smem_set) {
        cudaFuncSetAttribute(mega_tail,
                             cudaFuncAttributeMaxDynamicSharedMemorySize,
                             tail_smem);
        cudaStreamCreateWithFlags(&s2, cudaStreamNonBlocking);
        cudaEventCreateWithFlags(&evH, cudaEventDisableTiming);
        cudaEventCreateWithFlags(&evX, cudaEventDisableTiming);
        smem_set = 1;
    }

    prep_kernel<<<1, 32>>>(esrc, thetas);

    int GBt = (n + 127) / 128;
    int GA  = GBt / 2;
    int GB  = GBt - GA;
    int CB  = (E + 255) / 256;
    int nb  = (n + 1023) / 1024;

    // fat1: gemm rows [0, GA*128) || count histogram (+ flag zeroing)
    fat1<<<GA + CB, 256>>>(x, Win, bin, ph, n, edst, E, GA);

    // single-pass scan -> g_off
    scan_kernel<<<nb, 1024>>>(n);

    // fat2: gemm rows [GA*128, n) || scatter.  h complete after this.
    fat2<<<GB + CB, 256>>>(x, Win, bin, ph, n, esrc, edst, ev, E, GA, GB);

    // fork: xproj = h @ Wx + bWx on side stream, overlapped with spmm hops
    cudaEventRecord(evH, 0);
    cudaStreamWaitEvent(s2, evH, 0);
    gemm64<<<GBt, 256, 0, s2>>>(ph, Wx, bWx, pxp, n);
    cudaEventRecord(evX, s2);

    // hops 1, 2 on main stream (2 rows/warp, float4 halves, csr prefetch)
    int warps = (n + 1) / 2;
    int sb = (warps * 32 + 255) / 256;
    spmm_csr<<<sb, 256>>>(ph,  pT1, n);
    spmm_csr<<<sb, 256>>>(pT1, pT2, n);

    // join, then fused hop-3 + poly + attention + MLP
    cudaStreamWaitEvent(0, evX, 0);
    mega_tail<<<(n + 63) / 64, 256, tail_smem>>>(
        ph, pT1, pT2, pxp, Wb, bWb, vc,
        W1, b1, W2, b2, W3, b3, (float*)d_out, n);
}

// round 11
// speedup vs baseline: 1.0225x; 1.0225x over previous
#include <cuda_runtime.h>
#include <cstdint>

// ---------------------------------------------------------------------------
// NodeBernNet fixed shapes: N=100000, E=1600000, C_IN=128, C=64, F=2, K+1=4.
// R11: R9 structure (no stream fork, tail computes xp itself) + ONE change:
// software-pipelined csr prefetch in the gather loop.
// ---------------------------------------------------------------------------

#define NMAX 100000
#define EMAX 1600000
#define CDIM 64

__device__ __align__(256) float g_h [NMAX * CDIM];
__device__ __align__(256) float g_T1[NMAX * CDIM];
__device__ __align__(256) float g_T2[NMAX * CDIM];
// CSR scratch
__device__ int g_cnt[NMAX];                 // count adds, scatter subtracts -> 0
__device__ int g_off[NMAX + 1];
__device__ unsigned long long g_pack[128];  // lookback {flag<<32 | aggregate}
__device__ __align__(16) int2 g_csr[EMAX];  // {src, val bits}

__device__ float g_coef[8];   // thetas @ BCOEF, [F=2][K+1=4]
__device__ int   g_is64;

// ---------------------------------------------------------------------------
__global__ void prep_kernel(const void* __restrict__ esrc,
                            const float* __restrict__ thetas)
{
    if (threadIdx.x == 0) {
        const int* w = (const int*)esrc;
        g_is64 = (w[1] == 0 && w[3] == 0 && w[5] == 0 && w[7] == 0) ? 1 : 0;
        const float B[4][4] = {
            {1.f, -3.f,  3.f, -1.f},
            {0.f,  3.f, -6.f,  3.f},
            {0.f,  0.f,  3.f, -3.f},
            {0.f,  0.f,  0.f,  1.f}};
        for (int f = 0; f < 2; f++)
            for (int k = 0; k < 4; k++) {
                float s = 0.f;
                for (int j = 0; j < 4; j++) s += thetas[f * 4 + j] * B[j][k];
                g_coef[f * 4 + k] = s;
            }
    }
}

// ---------------------------------------------------------------------------
// GEMM body: h = relu(x @ W_in + b_in), 128-row tile at m0.
// ---------------------------------------------------------------------------
__device__ __forceinline__ void gemm_body(const float* __restrict__ A,
                                          const float* __restrict__ W,
                                          const float* __restrict__ bias,
                                          float* __restrict__ C, int M, int m0)
{
    __shared__ float As[16][132];
    __shared__ float Bs[16][68];

    const int tid = threadIdx.x;
    const int tx = tid & 15;
    const int ty = tid >> 4;

    float acc[8][4] = {};

    for (int k0 = 0; k0 < 128; k0 += 16) {
        #pragma unroll
        for (int r = 0; r < 2; r++) {
            int i = tid + r * 256;
            int row = i >> 2, kq = i & 3;
            int gm = m0 + row;
            float4 v = make_float4(0.f, 0.f, 0.f, 0.f);
            if (gm < M) v = *(const float4*)(A + (size_t)gm * 128 + k0 + kq * 4);
            As[kq * 4 + 0][row] = v.x;
            As[kq * 4 + 1][row] = v.y;
            As[kq * 4 + 2][row] = v.z;
            As[kq * 4 + 3][row] = v.w;
        }
        {
            int k = tid >> 4, nn = (tid & 15) * 4;
            float4 v = *(const float4*)(W + (size_t)(k0 + k) * 64 + nn);
            Bs[k][nn + 0] = v.x; Bs[k][nn + 1] = v.y;
            Bs[k][nn + 2] = v.z; Bs[k][nn + 3] = v.w;
        }
        __syncthreads();
        #pragma unroll
        for (int kk = 0; kk < 16; kk++) {
            float4 a0 = *(const float4*)&As[kk][ty * 8];
            float4 a1 = *(const float4*)&As[kk][ty * 8 + 4];
            float4 b  = *(const float4*)&Bs[kk][tx * 4];
            float am[8] = {a0.x, a0.y, a0.z, a0.w, a1.x, a1.y, a1.z, a1.w};
            float bn[4] = {b.x, b.y, b.z, b.w};
            #pragma unroll
            for (int i = 0; i < 8; i++)
                #pragma unroll
                for (int j = 0; j < 4; j++)
                    acc[i][j] += am[i] * bn[j];
        }
        __syncthreads();
    }

    int nn = tx * 4;
    float4 bv = *(const float4*)(bias + nn);
    #pragma unroll
    for (int i = 0; i < 8; i++) {
        int gm = m0 + ty * 8 + i;
        if (gm >= M) continue;
        float4 o;
        o.x = fmaxf(acc[i][0] + bv.x, 0.f);
        o.y = fmaxf(acc[i][1] + bv.y, 0.f);
        o.z = fmaxf(acc[i][2] + bv.z, 0.f);
        o.w = fmaxf(acc[i][3] + bv.w, 0.f);
        *(float4*)(C + (size_t)gm * 64 + nn) = o;
    }
}

// ---------------------------------------------------------------------------
// fat1: blocks [0,GA) gemm rows [0,GA*128); blocks [GA,..) count histogram.
// ---------------------------------------------------------------------------
__global__ void fat1(const float* __restrict__ A,
                     const float* __restrict__ W,
                     const float* __restrict__ bias,
                     float* __restrict__ C, int M,
                     const void* __restrict__ edst, int E, int GA)
{
    if ((int)blockIdx.x >= GA) {
        if ((int)blockIdx.x == GA && threadIdx.x < 128)
            g_pack[threadIdx.x] = 0ULL;
        int e = (blockIdx.x - GA) * blockDim.x + threadIdx.x;
        if (e < E) {
            int dst = g_is64 ? (int)((const long long*)edst)[e]
                             : ((const int*)edst)[e];
            atomicAdd(&g_cnt[dst], 1);
        }
        return;
    }
    gemm_body(A, W, bias, C, M, blockIdx.x * 128);
}

// ---------------------------------------------------------------------------
// Single-pass scan with decoupled lookback.
// ---------------------------------------------------------------------------
__global__ void scan_kernel(int n)
{
    __shared__ int warp_sums[32];
    __shared__ int s_prefix;

    int t = threadIdx.x, bid = blockIdx.x;
    int i = bid * 1024 + t;
    int lane = t & 31, wid = t >> 5;

    int x = (i < n) ? g_cnt[i] : 0;
    #pragma unroll
    for (int o = 1; o < 32; o <<= 1) {
        int y = __shfl_up_sync(0xffffffffu, x, o);
        if (lane >= o) x += y;
    }
    if (lane == 31) warp_sums[wid] = x;
    __syncthreads();
    if (wid == 0) {
        int s = warp_sums[lane];
        #pragma unroll
        for (int o = 1; o < 32; o <<= 1) {
            int y = __shfl_up_sync(0xffffffffu, s, o);
            if (lane >= o) s += y;
        }
        warp_sums[lane] = s;
    }
    __syncthreads();
    int incl = x + (wid > 0 ? warp_sums[wid - 1] : 0);
    int aggregate = warp_sums[31];

    if (t == 0) {
        if (bid == 0) {
            *(volatile unsigned long long*)&g_pack[0] =
                (2ULL << 32) | (unsigned)aggregate;
            s_prefix = 0;
        } else {
            *(volatile unsigned long long*)&g_pack[bid] =
                (1ULL << 32) | (unsigned)aggregate;
            int sum = 0;
            for (int j = bid - 1; j >= 0; j--) {
                unsigned long long p;
                do { p = *(volatile unsigned long long*)&g_pack[j]; }
                while ((p >> 32) == 0ULL);
                sum += (int)(unsigned)p;
                if ((p >> 32) == 2ULL) break;
            }
            *(volatile unsigned long long*)&g_pack[bid] =
                (2ULL << 32) | (unsigned)(sum + aggregate);
            s_prefix = sum;
        }
    }
    __syncthreads();
    if (i < n) g_off[i + 1] = s_prefix + incl;
    if (i == 0) g_off[0] = 0;
}

// ---------------------------------------------------------------------------
// fat2: blocks [0,GB) gemm rows from GA*128; rest scatter (self-zeroing cnt).
// ---------------------------------------------------------------------------
__global__ void fat2(const float* __restrict__ A,
                     const float* __restrict__ W,
                     const float* __restrict__ bias,
                     float* __restrict__ C, int M,
                     const void* __restrict__ esrc,
                     const void* __restrict__ edst,
                     const float* __restrict__ ev,
                     int E, int GA, int GB)
{
    if ((int)blockIdx.x >= GB) {
        int e = (blockIdx.x - GB) * 256 + threadIdx.x;
        if (e < E) {
            int src, dst;
            if (g_is64) {
                src = (int)((const long long*)esrc)[e];
                dst = (int)((const long long*)edst)[e];
            } else {
                src = ((const int*)esrc)[e];
                dst = ((const int*)edst)[e];
            }
            int old = atomicSub(&g_cnt[dst], 1);   // old in [1, cnt]
            g_csr[g_off[dst + 1] - old] = make_int2(src, __float_as_int(ev[e]));
        }
        return;
    }
    gemm_body(A, W, bias, C, M, (GA + blockIdx.x) * 128);
}

// ---------------------------------------------------------------------------
// CSR row gather-accumulate: float4 per 16-lane half, software-pipelined
// csr prefetch (batch k+1's csr loads issue before batch k's gathers).
// ---------------------------------------------------------------------------
__device__ __forceinline__ float4 spmm_row_acc(const float* __restrict__ hin,
                                               int s, int e, int lane16)
{
    float4 acc = make_float4(0.f, 0.f, 0.f, 0.f);
    int nb = (e - s) >> 2;
    int i = s;
    if (nb > 0) {
        int2 c0 = __ldg(&g_csr[i]);
        int2 c1 = __ldg(&g_csr[i + 1]);
        int2 c2 = __ldg(&g_csr[i + 2]);
        int2 c3 = __ldg(&g_csr[i + 3]);
        for (int b = 1; b < nb; b++) {
            int j = s + b * 4;
            int2 n0 = __ldg(&g_csr[j]);
            int2 n1 = __ldg(&g_csr[j + 1]);
            int2 n2 = __ldg(&g_csr[j + 2]);
            int2 n3 = __ldg(&g_csr[j + 3]);
            float4 h0 = *((const float4*)(hin + (size_t)c0.x * CDIM) + lane16);
            float4 h1 = *((const float4*)(hin + (size_t)c1.x * CDIM) + lane16);
            float4 h2 = *((const float4*)(hin + (size_t)c2.x * CDIM) + lane16);
            float4 h3 = *((const float4*)(hin + (size_t)c3.x * CDIM) + lane16);
            float v0 = __int_as_float(c0.y), v1 = __int_as_float(c1.y);
            float v2 = __int_as_float(c2.y), v3 = __int_as_float(c3.y);
            acc.x += v0 * h0.x + v1 * h1.x + v2 * h2.x + v3 * h3.x;
            acc.y += v0 * h0.y + v1 * h1.y + v2 * h2.y + v3 * h3.y;
            acc.z += v0 * h0.z + v1 * h1.z + v2 * h2.z + v3 * h3.z;
            acc.w += v0 * h0.w + v1 * h1.w + v2 * h2.w + v3 * h3.w;
            c0 = n0; c1 = n1; c2 = n2; c3 = n3;
        }
        {
            float4 h0 = *((const float4*)(hin + (size_t)c0.x * CDIM) + lane16);
            float4 h1 = *((const float4*)(hin + (size_t)c1.x * CDIM) + lane16);
            float4 h2 = *((const float4*)(hin + (size_t)c2.x * CDIM) + lane16);
            float4 h3 = *((const float4*)(hin + (size_t)c3.x * CDIM) + lane16);
            float v0 = __int_as_float(c0.y), v1 = __int_as_float(c1.y);
            float v2 = __int_as_float(c2.y), v3 = __int_as_float(c3.y);
            acc.x += v0 * h0.x + v1 * h1.x + v2 * h2.x + v3 * h3.x;
            acc.y += v0 * h0.y + v1 * h1.y + v2 * h2.y + v3 * h3.y;
            acc.z += v0 * h0.z + v1 * h1.z + v2 * h2.z + v3 * h3.z;
            acc.w += v0 * h0.w + v1 * h1.w + v2 * h2.w + v3 * h3.w;
        }
        i = s + nb * 4;
    }
    for (; i < e; i++) {
        int2 p0 = __ldg(&g_csr[i]);
        float v0 = __int_as_float(p0.y);
        float4 h0 = *((const float4*)(hin + (size_t)p0.x * CDIM) + lane16);
        acc.x += v0 * h0.x; acc.y += v0 * h0.y;
        acc.z += v0 * h0.z; acc.w += v0 * h0.w;
    }
    return acc;
}

__global__ void spmm_csr(const float* __restrict__ hin,
                         float* __restrict__ hout, int n)
{
    int w = (blockIdx.x * blockDim.x + threadIdx.x) >> 5;
    int lane = threadIdx.x & 31;
    int r = w * 2 + (lane >> 4);
    if (r >= n) return;
    int lane16 = lane & 15;
    float4 acc = spmm_row_acc(hin, g_off[r], g_off[r + 1], lane16);
    *((float4*)(hout + (size_t)r * CDIM) + lane16) = acc;
}

// ---------------------------------------------------------------------------
// Mega-tail (R9 form): hop-3 gather + poly -> Ps; xp = h@Wx in-block;
// score; softmax; res; 3-layer MLP head. 64 nodes per 256-thread block.
// ---------------------------------------------------------------------------
#define TAIL_SMEM_FLOATS (64*68 + 64*68 + 64*137 + 128 + 64 + 64)

__global__ void mega_tail(const float* __restrict__ h,
                          const float* __restrict__ t1,
                          const float* __restrict__ t2,
                          const float* __restrict__ Wx,
                          const float* __restrict__ bWx,
                          const float* __restrict__ Wb,
                          const float* __restrict__ bWb,
                          const float* __restrict__ vc,
                          const float* __restrict__ W1,
                          const float* __restrict__ b1,
                          const float* __restrict__ W2,
                          const float* __restrict__ b2,
                          const float* __restrict__ W3,
                          const float* __restrict__ b3,
                          float* __restrict__ out, int nn)
{
    extern __shared__ float sm[];
    float* As  = sm;                 // [k][m] 64x68
    float* Ws  = As + 64 * 68;       // [k][n] 64x68
    float* Ps  = Ws + 64 * 68;       // [c][row] 64x137 (poly, 128 rows)
    float* Ss  = Ps + 64 * 137;      // 128 scores
    float* Sa0 = Ss + 128;
    float* Sa1 = Sa0 + 64;

    const int tid = threadIdx.x;
    const int b0 = blockIdx.x * 64;
    const int tx = tid & 15;
    const int ty = tid >> 4;

    // ---- loaders: h rows -> As (transposed), Wx -> Ws ----
    #pragma unroll
    for (int r = 0; r < 4; r++) {
        int i = tid + r * 256;
        int m = i >> 4, q = i & 15;
        int gn = b0 + m;
        float4 v = make_float4(0.f, 0.f, 0.f, 0.f);
        if (gn < nn) v = *((const float4*)(h + (size_t)gn * 64) + q);
        As[(q * 4 + 0) * 68 + m] = v.x;
        As[(q * 4 + 1) * 68 + m] = v.y;
        As[(q * 4 + 2) * 68 + m] = v.z;
        As[(q * 4 + 3) * 68 + m] = v.w;
    }
    #pragma unroll
    for (int r = 0; r < 4; r++) {
        int i = tid + r * 256;
        int k = i >> 4, nq = (i & 15) * 4;
        float4 v = *(const float4*)(Wx + (size_t)k * 64 + nq);
        Ws[k * 68 + nq]     = v.x; Ws[k * 68 + nq + 1] = v.y;
        Ws[k * 68 + nq + 2] = v.z; Ws[k * 68 + nq + 3] = v.w;
    }

    // ---- stage A: hop-3 gather + poly, 2 rows per warp -> Ps ----
    {
        int wid = tid >> 5;
        int lane = tid & 31;
        int lane16 = lane & 15;
        float c00 = g_coef[0], c01 = g_coef[1], c02 = g_coef[2], c03 = g_coef[3];
        float c10 = g_coef[4], c11 = g_coef[5], c12 = g_coef[6], c13 = g_coef[7];
        #pragma unroll
        for (int it = 0; it < 4; it++) {
            int local = wid * 8 + it * 2 + (lane >> 4);
            int r = b0 + local;
            float4 p0 = make_float4(0.f, 0.f, 0.f, 0.f);
            float4 p1 = make_float4(0.f, 0.f, 0.f, 0.f);
            if (r < nn) {
                float4 d = spmm_row_acc(t2, g_off[r], g_off[r + 1], lane16);
                float4 a = *((const float4*)(h  + (size_t)r * CDIM) + lane16);
                float4 b = *((const float4*)(t1 + (size_t)r * CDIM) + lane16);
                float4 c = *((const float4*)(t2 + (size_t)r * CDIM) + lane16);
                p0.x = c00*a.x + c01*b.x + c02*c.x + c03*d.x;
                p0.y = c00*a.y + c01*b.y + c02*c.y + c03*d.y;
                p0.z = c00*a.z + c01*b.z + c02*c.z + c03*d.z;
                p0.w = c00*a.w + c01*b.w + c02*c.w + c03*d.w;
                p1.x = c10*a.x + c11*b.x + c12*c.x + c13*d.x;
                p1.y = c10*a.y + c11*b.y + c12*c.y + c13*d.y;
                p1.z = c10*a.z + c11*b.z + c12*c.z + c13*d.z;
                p1.w = c10*a.w + c11*b.w + c12*c.w + c13*d.w;
            }
            int cb = lane16 * 4;
            int m2 = 2 * local;
            Ps[(cb + 0) * 137 + m2] = p0.x; Ps[(cb + 0) * 137 + m2 + 1] = p1.x;
            Ps[(cb + 1) * 137 + m2] = p0.y; Ps[(cb + 1) * 137 + m2 + 1] = p1.y;
            Ps[(cb + 2) * 137 + m2] = p0.z; Ps[(cb + 2) * 137 + m2 + 1] = p1.z;
            Ps[(cb + 3) * 137 + m2] = p0.w; Ps[(cb + 3) * 137 + m2 + 1] = p1.w;
        }
    }
    __syncthreads();

    // ---- stage 1: xp = h @ Wx + bWx (register 4x4) ----
    float xp[4][4] = {};
    #pragma unroll
    for (int kk = 0; kk < 64; kk++) {
        float4 a = *(const float4*)&As[kk * 68 + ty * 4];
        float4 b = *(const float4*)&Ws[kk * 68 + tx * 4];
        float am[4] = {a.x, a.y, a.z, a.w};
        float bn[4] = {b.x, b.y, b.z, b.w};
        #pragma unroll
        for (int i = 0; i < 4; i++)
            #pragma unroll
            for (int j = 0; j < 4; j++)
                xp[i][j] += am[i] * bn[j];
    }
    {
        float4 bx = *(const float4*)(bWx + tx * 4);
        #pragma unroll
        for (int i = 0; i < 4; i++) {
            xp[i][0] += bx.x; xp[i][1] += bx.y;
            xp[i][2] += bx.z; xp[i][3] += bx.w;
        }
    }
    __syncthreads();

    // load Wb -> Ws
    #pragma unroll
    for (int r = 0; r < 4; r++) {
        int i = tid + r * 256;
        int k = i >> 4, nq = (i & 15) * 4;
        float4 v = *(const float4*)(Wb + (size_t)k * 64 + nq);
        Ws[k * 68 + nq]     = v.x; Ws[k * 68 + nq + 1] = v.y;
        Ws[k * 68 + nq + 2] = v.z; Ws[k * 68 + nq + 3] = v.w;
    }
    __syncthreads();

    // ---- stage 2: scores ----
    {
        float acc2[8][4] = {};
        #pragma unroll
        for (int kk = 0; kk < 64; kk++) {
            float4 b = *(const float4*)&Ws[kk * 68 + tx * 4];
            float bn[4] = {b.x, b.y, b.z, b.w};
            const float* pr = &Ps[kk * 137 + ty * 8];
            #pragma unroll
            for (int i = 0; i < 8; i++) {
                float av = pr[i];
                acc2[i][0] += av * bn[0];
                acc2[i][1] += av * bn[1];
                acc2[i][2] += av * bn[2];
                acc2[i][3] += av * bn[3];
            }
        }
        float4 bb = *(const float4*)(bWb + tx * 4);
        float4 vv = *(const float4*)(vc + tx * 4);
        #pragma unroll
        for (int i = 0; i < 8; i++) {
            int h2 = i >> 1;
            float part;
            part  = tanhf(acc2[i][0] + bb.x + xp[h2][0]) * vv.x;
            part += tanhf(acc2[i][1] + bb.y + xp[h2][1]) * vv.y;
            part += tanhf(acc2[i][2] + bb.z + xp[h2][2]) * vv.z;
            part += tanhf(acc2[i][3] + bb.w + xp[h2][3]) * vv.w;
            #pragma unroll
            for (int o = 8; o > 0; o >>= 1)
                part += __shfl_xor_sync(0xffffffffu, part, o);
            if (tx == 0) Ss[ty * 8 + i] = part;
        }
    }
    __syncthreads();

    // ---- softmax per node ----
    if (tid < 64) {
        float s0 = Ss[2 * tid], s1 = Ss[2 * tid + 1];
        float m = fmaxf(s0, s1);
        float e0 = expf(s0 - m), e1 = expf(s1 - m);
        float inv = 1.f / (e0 + e1);
        Sa0[tid] = e0 * inv;
        Sa1[tid] = e1 * inv;
    }
    __syncthreads();

    // ---- res -> As, W1 -> Ws ----
    #pragma unroll
    for (int r = 0; r < 16; r++) {
        int i = tid + r * 256;
        int c = i >> 6, m = i & 63;
        As[c * 68 + m] = Sa0[m] * Ps[c * 137 + 2 * m]
                       + Sa1[m] * Ps[c * 137 + 2 * m + 1];
    }
    #pragma unroll
    for (int r = 0; r < 4; r++) {
        int i = tid + r * 256;
        int k = i >> 4, nq = (i & 15) * 4;
        float4 v = *(const float4*)(W1 + (size_t)k * 64 + nq);
        Ws[k * 68 + nq]     = v.x; Ws[k * 68 + nq + 1] = v.y;
        Ws[k * 68 + nq + 2] = v.z; Ws[k * 68 + nq + 3] = v.w;
    }
    __syncthreads();

    // ---- y1 = relu(res @ W1 + b1) ----
    float acc[4][4] = {};
    #pragma unroll
    for (int kk = 0; kk < 64; kk++) {
        float4 a = *(const float4*)&As[kk * 68 + ty * 4];
        float4 b = *(const float4*)&Ws[kk * 68 + tx * 4];
        float am[4] = {a.x, a.y, a.z, a.w};
        float bn[4] = {b.x, b.y, b.z, b.w};
        #pragma unroll
        for (int i = 0; i < 4; i++)
            #pragma unroll
            for (int j = 0; j < 4; j++)
                acc[i][j] += am[i] * bn[j];
    }
    __syncthreads();

    {
        float4 bv = *(const float4*)(b1 + tx * 4);
        float bbv[4] = {bv.x, bv.y, bv.z, bv.w};
        #pragma unroll
        for (int i = 0; i < 4; i++)
            #pragma unroll
            for (int j = 0; j < 4; j++)
                As[(tx * 4 + j) * 68 + ty * 4 + i] = fmaxf(acc[i][j] + bbv[j], 0.f);
    }
    #pragma unroll
    for (int r = 0; r < 2; r++) {
        int i = tid + r * 256;
        int k = i >> 3, nq = (i & 7) * 4;
        float4 v = *(const float4*)(W2 + (size_t)k * 32 + nq);
        Ws[k * 68 + nq]     = v.x; Ws[k * 68 + nq + 1] = v.y;
        Ws[k * 68 + nq + 2] = v.z; Ws[k * 68 + nq + 3] = v.w;
    }
    __syncthreads();

    // ---- y2 = relu(y1@W2+b2); out = y2@W3+b3 ----
    const int tx2 = tid & 15;
    const int ty2 = tid >> 4;
    float acc3[4][2] = {};
    #pragma unroll
    for (int kk = 0; kk < 64; kk++) {
        float4 a = *(const float4*)&As[kk * 68 + ty2 * 4];
        float b0v = Ws[kk * 68 + tx2 * 2];
        float b1v = Ws[kk * 68 + tx2 * 2 + 1];
        float am[4] = {a.x, a.y, a.z, a.w};
        #pragma unroll
        for (int i = 0; i < 4; i++) {
            acc3[i][0] += am[i] * b0v;
            acc3[i][1] += am[i] * b1v;
        }
    }
    float bb0 = b2[tx2 * 2], bb1 = b2[tx2 * 2 + 1];
    float w00 = W3[(tx2 * 2) * 2],     w01 = W3[(tx2 * 2) * 2 + 1];
    float w10 = W3[(tx2 * 2 + 1) * 2], w11 = W3[(tx2 * 2 + 1) * 2 + 1];

    #pragma unroll
    for (int i = 0; i < 4; i++) {
        float y0 = fmaxf(acc3[i][0] + bb0, 0.f);
        float y1v = fmaxf(acc3[i][1] + bb1, 0.f);
        float s0 = y0 * w00 + y1v * w10;
        float s1 = y0 * w01 + y1v * w11;
        #pragma unroll
        for (int o = 8; o > 0; o >>= 1) {
            s0 += __shfl_xor_sync(0xffffffffu, s0, o);
            s1 += __shfl_xor_sync(0xffffffffu, s1, o);
        }
        int gm = b0 + ty2 * 4 + i;
        if (tx2 == 0 && gm < nn) {
            out[gm * 2]     = s0 + b3[0];
            out[gm * 2 + 1] = s1 + b3[1];
        }
    }
}

// ---------------------------------------------------------------------------
extern "C" void kernel_launch(void* const* d_in, const int* in_sizes, int n_in,
                              void* d_out, int out_size)
{
    const float* x      = (const float*)d_in[0];
    const void*  esrc   = d_in[1];
    const void*  edst   = d_in[2];
    const float* ev     = (const float*)d_in[3];
    const float* Win    = (const float*)d_in[4];
    const float* bin    = (const float*)d_in[5];
    const float* thetas = (const float*)d_in[6];
    const float* Wb     = (const float*)d_in[7];
    const float* bWb    = (const float*)d_in[8];
    const float* Wx     = (const float*)d_in[9];
    const float* bWx    = (const float*)d_in[10];
    const float* vc     = (const float*)d_in[11];
    const float* W1     = (const float*)d_in[12];
    const float* b1     = (const float*)d_in[13];
    const float* W2     = (const float*)d_in[14];
    const float* b2     = (const float*)d_in[15];
    const float* W3     = (const float*)d_in[16];
    const float* b3     = (const float*)d_in[17];

    int n = in_sizes[0] / 128;
    int E = in_sizes[3];

    float *ph, *pT1, *pT2;
    cudaGetSymbolAddress((void**)&ph,  g_h);
    cudaGetSymbolAddress((void**)&pT1, g_T1);
    cudaGetSymbolAddress((void**)&pT2, g_T2);

    static int smem_set = 0;
    const int tail_smem = TAIL_SMEM_FLOATS * (int)sizeof(float);
    if (!smem_set) {
        cudaFuncSetAttribute(mega_tail,
                             cudaFuncAttributeMaxDynamicSharedMemorySize,
                             tail_smem);
        smem_set = 1;
    }

    prep_kernel<<<1, 32>>>(esrc, thetas);

    int GBt = (n + 127) / 128;
    int GA  = GBt / 2;
    int GB  = GBt - GA;
    int CB  = (E + 255) / 256;
    int nb  = (n + 1023) / 1024;

    // fat1: gemm rows [0, GA*128) || count histogram (+ flag zeroing)
    fat1<<<GA + CB, 256>>>(x, Win, bin, ph, n, edst, E, GA);

    // single-pass scan -> g_off
    scan_kernel<<<nb, 1024>>>(n);

    // fat2: gemm rows [GA*128, n) || scatter
    fat2<<<GB + CB, 256>>>(x, Win, bin, ph, n, esrc, edst, ev, E, GA, GB);

    // hops 1, 2 (2 rows/warp, float4 halves, csr prefetch)
    int warps = (n + 1) / 2;
    int sb = (warps * 32 + 255) / 256;
    spmm_csr<<<sb, 256>>>(ph,  pT1, n);
    spmm_csr<<<sb, 256>>>(pT1, pT2, n);

    // fused hop-3 + poly + attention + MLP
    mega_tail<<<(n + 63) / 64, 256, tail_smem>>>(
        ph, pT1, pT2, Wx, bWx, Wb, bWb, vc,
        W1, b1, W2, b2, W3, b3, (float*)d_out, n);
}

// round 12
// speedup vs baseline: 1.0982x; 1.0741x over previous
#include <cuda_runtime.h>
#include <cstdint>

// ---------------------------------------------------------------------------
// NodeBernNet fixed shapes: N=100000, E=1600000, C_IN=128, C=64, F=2, K+1=4.
// R12: R9 structure; tail gather = plain unroll-4; spmm hops = flat unroll-8
// (8 gathers in flight per half-warp).
// ---------------------------------------------------------------------------

#define NMAX 100000
#define EMAX 1600000
#define CDIM 64

__device__ __align__(256) float g_h [NMAX * CDIM];
__device__ __align__(256) float g_T1[NMAX * CDIM];
__device__ __align__(256) float g_T2[NMAX * CDIM];
// CSR scratch
__device__ int g_cnt[NMAX];                 // count adds, scatter subtracts -> 0
__device__ int g_off[NMAX + 1];
__device__ unsigned long long g_pack[128];  // lookback {flag<<32 | aggregate}
__device__ __align__(16) int2 g_csr[EMAX];  // {src, val bits}

__device__ float g_coef[8];   // thetas @ BCOEF, [F=2][K+1=4]
__device__ int   g_is64;

// ---------------------------------------------------------------------------
__global__ void prep_kernel(const void* __restrict__ esrc,
                            const float* __restrict__ thetas)
{
    if (threadIdx.x == 0) {
        const int* w = (const int*)esrc;
        g_is64 = (w[1] == 0 && w[3] == 0 && w[5] == 0 && w[7] == 0) ? 1 : 0;
        const float B[4][4] = {
            {1.f, -3.f,  3.f, -1.f},
            {0.f,  3.f, -6.f,  3.f},
            {0.f,  0.f,  3.f, -3.f},
            {0.f,  0.f,  0.f,  1.f}};
        for (int f = 0; f < 2; f++)
            for (int k = 0; k < 4; k++) {
                float s = 0.f;
                for (int j = 0; j < 4; j++) s += thetas[f * 4 + j] * B[j][k];
                g_coef[f * 4 + k] = s;
            }
    }
}

// ---------------------------------------------------------------------------
// GEMM body: h = relu(x @ W_in + b_in), 128-row tile at m0.
// ---------------------------------------------------------------------------
__device__ __forceinline__ void gemm_body(const float* __restrict__ A,
                                          const float* __restrict__ W,
                                          const float* __restrict__ bias,
                                          float* __restrict__ C, int M, int m0)
{
    __shared__ float As[16][132];
    __shared__ float Bs[16][68];

    const int tid = threadIdx.x;
    const int tx = tid & 15;
    const int ty = tid >> 4;

    float acc[8][4] = {};

    for (int k0 = 0; k0 < 128; k0 += 16) {
        #pragma unroll
        for (int r = 0; r < 2; r++) {
            int i = tid + r * 256;
            int row = i >> 2, kq = i & 3;
            int gm = m0 + row;
            float4 v = make_float4(0.f, 0.f, 0.f, 0.f);
            if (gm < M) v = *(const float4*)(A + (size_t)gm * 128 + k0 + kq * 4);
            As[kq * 4 + 0][row] = v.x;
            As[kq * 4 + 1][row] = v.y;
            As[kq * 4 + 2][row] = v.z;
            As[kq * 4 + 3][row] = v.w;
        }
        {
            int k = tid >> 4, nn = (tid & 15) * 4;
            float4 v = *(const float4*)(W + (size_t)(k0 + k) * 64 + nn);
            Bs[k][nn + 0] = v.x; Bs[k][nn + 1] = v.y;
            Bs[k][nn + 2] = v.z; Bs[k][nn + 3] = v.w;
        }
        __syncthreads();
        #pragma unroll
        for (int kk = 0; kk < 16; kk++) {
            float4 a0 = *(const float4*)&As[kk][ty * 8];
            float4 a1 = *(const float4*)&As[kk][ty * 8 + 4];
            float4 b  = *(const float4*)&Bs[kk][tx * 4];
            float am[8] = {a0.x, a0.y, a0.z, a0.w, a1.x, a1.y, a1.z, a1.w};
            float bn[4] = {b.x, b.y, b.z, b.w};
            #pragma unroll
            for (int i = 0; i < 8; i++)
                #pragma unroll
                for (int j = 0; j < 4; j++)
                    acc[i][j] += am[i] * bn[j];
        }
        __syncthreads();
    }

    int nn = tx * 4;
    float4 bv = *(const float4*)(bias + nn);
    #pragma unroll
    for (int i = 0; i < 8; i++) {
        int gm = m0 + ty * 8 + i;
        if (gm >= M) continue;
        float4 o;
        o.x = fmaxf(acc[i][0] + bv.x, 0.f);
        o.y = fmaxf(acc[i][1] + bv.y, 0.f);
        o.z = fmaxf(acc[i][2] + bv.z, 0.f);
        o.w = fmaxf(acc[i][3] + bv.w, 0.f);
        *(float4*)(C + (size_t)gm * 64 + nn) = o;
    }
}

// ---------------------------------------------------------------------------
// fat1: blocks [0,GA) gemm rows [0,GA*128); blocks [GA,..) count histogram.
// ---------------------------------------------------------------------------
__global__ void fat1(const float* __restrict__ A,
                     const float* __restrict__ W,
                     const float* __restrict__ bias,
                     float* __restrict__ C, int M,
                     const void* __restrict__ edst, int E, int GA)
{
    if ((int)blockIdx.x >= GA) {
        if ((int)blockIdx.x == GA && threadIdx.x < 128)
            g_pack[threadIdx.x] = 0ULL;
        int e = (blockIdx.x - GA) * blockDim.x + threadIdx.x;
        if (e < E) {
            int dst = g_is64 ? (int)((const long long*)edst)[e]
                             : ((const int*)edst)[e];
            atomicAdd(&g_cnt[dst], 1);
        }
        return;
    }
    gemm_body(A, W, bias, C, M, blockIdx.x * 128);
}

// ---------------------------------------------------------------------------
// Single-pass scan with decoupled lookback.
// ---------------------------------------------------------------------------
__global__ void scan_kernel(int n)
{
    __shared__ int warp_sums[32];
    __shared__ int s_prefix;

    int t = threadIdx.x, bid = blockIdx.x;
    int i = bid * 1024 + t;
    int lane = t & 31, wid = t >> 5;

    int x = (i < n) ? g_cnt[i] : 0;
    #pragma unroll
    for (int o = 1; o < 32; o <<= 1) {
        int y = __shfl_up_sync(0xffffffffu, x, o);
        if (lane >= o) x += y;
    }
    if (lane == 31) warp_sums[wid] = x;
    __syncthreads();
    if (wid == 0) {
        int s = warp_sums[lane];
        #pragma unroll
        for (int o = 1; o < 32; o <<= 1) {
            int y = __shfl_up_sync(0xffffffffu, s, o);
            if (lane >= o) s += y;
        }
        warp_sums[lane] = s;
    }
    __syncthreads();
    int incl = x + (wid > 0 ? warp_sums[wid - 1] : 0);
    int aggregate = warp_sums[31];

    if (t == 0) {
        if (bid == 0) {
            *(volatile unsigned long long*)&g_pack[0] =
                (2ULL << 32) | (unsigned)aggregate;
            s_prefix = 0;
        } else {
            *(volatile unsigned long long*)&g_pack[bid] =
                (1ULL << 32) | (unsigned)aggregate;
            int sum = 0;
            for (int j = bid - 1; j >= 0; j--) {
                unsigned long long p;
                do { p = *(volatile unsigned long long*)&g_pack[j]; }
                while ((p >> 32) == 0ULL);
                sum += (int)(unsigned)p;
                if ((p >> 32) == 2ULL) break;
            }
            *(volatile unsigned long long*)&g_pack[bid] =
                (2ULL << 32) | (unsigned)(sum + aggregate);
            s_prefix = sum;
        }
    }
    __syncthreads();
    if (i < n) g_off[i + 1] = s_prefix + incl;
    if (i == 0) g_off[0] = 0;
}

// ---------------------------------------------------------------------------
// fat2: blocks [0,GB) gemm rows from GA*128; rest scatter (self-zeroing cnt).
// ---------------------------------------------------------------------------
__global__ void fat2(const float* __restrict__ A,
                     const float* __restrict__ W,
                     const float* __restrict__ bias,
                     float* __restrict__ C, int M,
                     const void* __restrict__ esrc,
                     const void* __restrict__ edst,
                     const float* __restrict__ ev,
                     int E, int GA, int GB)
{
    if ((int)blockIdx.x >= GB) {
        int e = (blockIdx.x - GB) * 256 + threadIdx.x;
        if (e < E) {
            int src, dst;
            if (g_is64) {
                src = (int)((const long long*)esrc)[e];
                dst = (int)((const long long*)edst)[e];
            } else {
                src = ((const int*)esrc)[e];
                dst = ((const int*)edst)[e];
            }
            int old = atomicSub(&g_cnt[dst], 1);   // old in [1, cnt]
            g_csr[g_off[dst + 1] - old] = make_int2(src, __float_as_int(ev[e]));
        }
        return;
    }
    gemm_body(A, W, bias, C, M, (GA + blockIdx.x) * 128);
}

// ---------------------------------------------------------------------------
// Plain unroll-4 gather (R9-proven) — used by the tail.
// ---------------------------------------------------------------------------
__device__ __forceinline__ float4 row_acc4(const float* __restrict__ hin,
                                           int s, int e, int lane16)
{
    float4 acc = make_float4(0.f, 0.f, 0.f, 0.f);
    int i = s;
    for (; i + 3 < e; i += 4) {
        int2 p0 = __ldg(&g_csr[i]);
        int2 p1 = __ldg(&g_csr[i + 1]);
        int2 p2 = __ldg(&g_csr[i + 2]);
        int2 p3 = __ldg(&g_csr[i + 3]);
        float4 h0 = *((const float4*)(hin + (size_t)p0.x * CDIM) + lane16);
        float4 h1 = *((const float4*)(hin + (size_t)p1.x * CDIM) + lane16);
        float4 h2 = *((const float4*)(hin + (size_t)p2.x * CDIM) + lane16);
        float4 h3 = *((const float4*)(hin + (size_t)p3.x * CDIM) + lane16);
        float v0 = __int_as_float(p0.y), v1 = __int_as_float(p1.y);
        float v2 = __int_as_float(p2.y), v3 = __int_as_float(p3.y);
        acc.x += v0 * h0.x + v1 * h1.x + v2 * h2.x + v3 * h3.x;
        acc.y += v0 * h0.y + v1 * h1.y + v2 * h2.y + v3 * h3.y;
        acc.z += v0 * h0.z + v1 * h1.z + v2 * h2.z + v3 * h3.z;
        acc.w += v0 * h0.w + v1 * h1.w + v2 * h2.w + v3 * h3.w;
    }
    for (; i < e; i++) {
        int2 p0 = __ldg(&g_csr[i]);
        float v0 = __int_as_float(p0.y);
        float4 h0 = *((const float4*)(hin + (size_t)p0.x * CDIM) + lane16);
        acc.x += v0 * h0.x; acc.y += v0 * h0.y;
        acc.z += v0 * h0.z; acc.w += v0 * h0.w;
    }
    return acc;
}

// ---------------------------------------------------------------------------
// spmm hop kernel: flat unroll-8 (8 gathers in flight per half-warp).
// ---------------------------------------------------------------------------
__global__ void spmm_csr(const float* __restrict__ hin,
                         float* __restrict__ hout, int n)
{
    int w = (blockIdx.x * blockDim.x + threadIdx.x) >> 5;
    int lane = threadIdx.x & 31;
    int r = w * 2 + (lane >> 4);
    if (r >= n) return;
    int lane16 = lane & 15;
    int s = g_off[r], e = g_off[r + 1];

    float4 acc = make_float4(0.f, 0.f, 0.f, 0.f);
    int i = s;
    for (; i + 7 < e; i += 8) {
        int2 p[8];
        #pragma unroll
        for (int u = 0; u < 8; u++) p[u] = __ldg(&g_csr[i + u]);
        float4 hv[8];
        #pragma unroll
        for (int u = 0; u < 8; u++)
            hv[u] = *((const float4*)(hin + (size_t)p[u].x * CDIM) + lane16);
        #pragma unroll
        for (int u = 0; u < 8; u++) {
            float v = __int_as_float(p[u].y);
            acc.x += v * hv[u].x;
            acc.y += v * hv[u].y;
            acc.z += v * hv[u].z;
            acc.w += v * hv[u].w;
        }
    }
    for (; i < e; i++) {
        int2 p0 = __ldg(&g_csr[i]);
        float v0 = __int_as_float(p0.y);
        float4 h0 = *((const float4*)(hin + (size_t)p0.x * CDIM) + lane16);
        acc.x += v0 * h0.x; acc.y += v0 * h0.y;
        acc.z += v0 * h0.z; acc.w += v0 * h0.w;
    }
    *((float4*)(hout + (size_t)r * CDIM) + lane16) = acc;
}

// ---------------------------------------------------------------------------
// Mega-tail (R9 form): hop-3 gather + poly -> Ps; xp = h@Wx in-block;
// score; softmax; res; 3-layer MLP head. 64 nodes per 256-thread block.
// ---------------------------------------------------------------------------
#define TAIL_SMEM_FLOATS (64*68 + 64*68 + 64*137 + 128 + 64 + 64)

__global__ void mega_tail(const float* __restrict__ h,
                          const float* __restrict__ t1,
                          const float* __restrict__ t2,
                          const float* __restrict__ Wx,
                          const float* __restrict__ bWx,
                          const float* __restrict__ Wb,
                          const float* __restrict__ bWb,
                          const float* __restrict__ vc,
                          const float* __restrict__ W1,
                          const float* __restrict__ b1,
                          const float* __restrict__ W2,
                          const float* __restrict__ b2,
                          const float* __restrict__ W3,
                          const float* __restrict__ b3,
                          float* __restrict__ out, int nn)
{
    extern __shared__ float sm[];
    float* As  = sm;                 // [k][m] 64x68
    float* Ws  = As + 64 * 68;       // [k][n] 64x68
    float* Ps  = Ws + 64 * 68;       // [c][row] 64x137 (poly, 128 rows)
    float* Ss  = Ps + 64 * 137;      // 128 scores
    float* Sa0 = Ss + 128;
    float* Sa1 = Sa0 + 64;

    const int tid = threadIdx.x;
    const int b0 = blockIdx.x * 64;
    const int tx = tid & 15;
    const int ty = tid >> 4;

    // ---- loaders: h rows -> As (transposed), Wx -> Ws ----
    #pragma unroll
    for (int r = 0; r < 4; r++) {
        int i = tid + r * 256;
        int m = i >> 4, q = i & 15;
        int gn = b0 + m;
        float4 v = make_float4(0.f, 0.f, 0.f, 0.f);
        if (gn < nn) v = *((const float4*)(h + (size_t)gn * 64) + q);
        As[(q * 4 + 0) * 68 + m] = v.x;
        As[(q * 4 + 1) * 68 + m] = v.y;
        As[(q * 4 + 2) * 68 + m] = v.z;
        As[(q * 4 + 3) * 68 + m] = v.w;
    }
    #pragma unroll
    for (int r = 0; r < 4; r++) {
        int i = tid + r * 256;
        int k = i >> 4, nq = (i & 15) * 4;
        float4 v = *(const float4*)(Wx + (size_t)k * 64 + nq);
        Ws[k * 68 + nq]     = v.x; Ws[k * 68 + nq + 1] = v.y;
        Ws[k * 68 + nq + 2] = v.z; Ws[k * 68 + nq + 3] = v.w;
    }

    // ---- stage A: hop-3 gather + poly, 2 rows per warp -> Ps ----
    {
        int wid = tid >> 5;
        int lane = tid & 31;
        int lane16 = lane & 15;
        float c00 = g_coef[0], c01 = g_coef[1], c02 = g_coef[2], c03 = g_coef[3];
        float c10 = g_coef[4], c11 = g_coef[5], c12 = g_coef[6], c13 = g_coef[7];
        #pragma unroll
        for (int it = 0; it < 4; it++) {
            int local = wid * 8 + it * 2 + (lane >> 4);
            int r = b0 + local;
            float4 p0 = make_float4(0.f, 0.f, 0.f, 0.f);
            float4 p1 = make_float4(0.f, 0.f, 0.f, 0.f);
            if (r < nn) {
                float4 d = row_acc4(t2, g_off[r], g_off[r + 1], lane16);
                float4 a = *((const float4*)(h  + (size_t)r * CDIM) + lane16);
                float4 b = *((const float4*)(t1 + (size_t)r * CDIM) + lane16);
                float4 c = *((const float4*)(t2 + (size_t)r * CDIM) + lane16);
                p0.x = c00*a.x + c01*b.x + c02*c.x + c03*d.x;
                p0.y = c00*a.y + c01*b.y + c02*c.y + c03*d.y;
                p0.z = c00*a.z + c01*b.z + c02*c.z + c03*d.z;
                p0.w = c00*a.w + c01*b.w + c02*c.w + c03*d.w;
                p1.x = c10*a.x + c11*b.x + c12*c.x + c13*d.x;
                p1.y = c10*a.y + c11*b.y + c12*c.y + c13*d.y;
                p1.z = c10*a.z + c11*b.z + c12*c.z + c13*d.z;
                p1.w = c10*a.w + c11*b.w + c12*c.w + c13*d.w;
            }
            int cb = lane16 * 4;
            int m2 = 2 * local;
            Ps[(cb + 0) * 137 + m2] = p0.x; Ps[(cb + 0) * 137 + m2 + 1] = p1.x;
            Ps[(cb + 1) * 137 + m2] = p0.y; Ps[(cb + 1) * 137 + m2 + 1] = p1.y;
            Ps[(cb + 2) * 137 + m2] = p0.z; Ps[(cb + 2) * 137 + m2 + 1] = p1.z;
            Ps[(cb + 3) * 137 + m2] = p0.w; Ps[(cb + 3) * 137 + m2 + 1] = p1.w;
        }
    }
    __syncthreads();

    // ---- stage 1: xp = h @ Wx + bWx (register 4x4) ----
    float xp[4][4] = {};
    #pragma unroll
    for (int kk = 0; kk < 64; kk++) {
        float4 a = *(const float4*)&As[kk * 68 + ty * 4];
        float4 b = *(const float4*)&Ws[kk * 68 + tx * 4];
        float am[4] = {a.x, a.y, a.z, a.w};
        float bn[4] = {b.x, b.y, b.z, b.w};
        #pragma unroll
        for (int i = 0; i < 4; i++)
            #pragma unroll
            for (int j = 0; j < 4; j++)
                xp[i][j] += am[i] * bn[j];
    }
    {
        float4 bx = *(const float4*)(bWx + tx * 4);
        #pragma unroll
        for (int i = 0; i < 4; i++) {
            xp[i][0] += bx.x; xp[i][1] += bx.y;
            xp[i][2] += bx.z; xp[i][3] += bx.w;
        }
    }
    __syncthreads();

    // load Wb -> Ws
    #pragma unroll
    for (int r = 0; r < 4; r++) {
        int i = tid + r * 256;
        int k = i >> 4, nq = (i & 15) * 4;
        float4 v = *(const float4*)(Wb + (size_t)k * 64 + nq);
        Ws[k * 68 + nq]     = v.x; Ws[k * 68 + nq + 1] = v.y;
        Ws[k * 68 + nq + 2] = v.z; Ws[k * 68 + nq + 3] = v.w;
    }
    __syncthreads();

    // ---- stage 2: scores ----
    {
        float acc2[8][4] = {};
        #pragma unroll
        for (int kk = 0; kk < 64; kk++) {
            float4 b = *(const float4*)&Ws[kk * 68 + tx * 4];
            float bn[4] = {b.x, b.y, b.z, b.w};
            const float* pr = &Ps[kk * 137 + ty * 8];
            #pragma unroll
            for (int i = 0; i < 8; i++) {
                float av = pr[i];
                acc2[i][0] += av * bn[0];
                acc2[i][1] += av * bn[1];
                acc2[i][2] += av * bn[2];
                acc2[i][3] += av * bn[3];
            }
        }
        float4 bb = *(const float4*)(bWb + tx * 4);
        float4 vv = *(const float4*)(vc + tx * 4);
        #pragma unroll
        for (int i = 0; i < 8; i++) {
            int h2 = i >> 1;
            float part;
            part  = tanhf(acc2[i][0] + bb.x + xp[h2][0]) * vv.x;
            part += tanhf(acc2[i][1] + bb.y + xp[h2][1]) * vv.y;
            part += tanhf(acc2[i][2] + bb.z + xp[h2][2]) * vv.z;
            part += tanhf(acc2[i][3] + bb.w + xp[h2][3]) * vv.w;
            #pragma unroll
            for (int o = 8; o > 0; o >>= 1)
                part += __shfl_xor_sync(0xffffffffu, part, o);
            if (tx == 0) Ss[ty * 8 + i] = part;
        }
    }
    __syncthreads();

    // ---- softmax per node ----
    if (tid < 64) {
        float s0 = Ss[2 * tid], s1 = Ss[2 * tid + 1];
        float m = fmaxf(s0, s1);
        float e0 = expf(s0 - m), e1 = expf(s1 - m);
        float inv = 1.f / (e0 + e1);
        Sa0[tid] = e0 * inv;
        Sa1[tid] = e1 * inv;
    }
    __syncthreads();

    // ---- res -> As, W1 -> Ws ----
    #pragma unroll
    for (int r = 0; r < 16; r++) {
        int i = tid + r * 256;
        int c = i >> 6, m = i & 63;
        As[c * 68 + m] = Sa0[m] * Ps[c * 137 + 2 * m]
                       + Sa1[m] * Ps[c * 137 + 2 * m + 1];
    }
    #pragma unroll
    for (int r = 0; r < 4; r++) {
        int i = tid + r * 256;
        int k = i >> 4, nq = (i & 15) * 4;
        float4 v = *(const float4*)(W1 + (size_t)k * 64 + nq);
        Ws[k * 68 + nq]     = v.x; Ws[k * 68 + nq + 1] = v.y;
        Ws[k * 68 + nq + 2] = v.z; Ws[k * 68 + nq + 3] = v.w;
    }
    __syncthreads();

    // ---- y1 = relu(res @ W1 + b1) ----
    float acc[4][4] = {};
    #pragma unroll
    for (int kk = 0; kk < 64; kk++) {
        float4 a = *(const float4*)&As[kk * 68 + ty * 4];
        float4 b = *(const float4*)&Ws[kk * 68 + tx * 4];
        float am[4] = {a.x, a.y, a.z, a.w};
        float bn[4] = {b.x, b.y, b.z, b.w};
        #pragma unroll
        for (int i = 0; i < 4; i++)
            #pragma unroll
            for (int j = 0; j < 4; j++)
                acc[i][j] += am[i] * bn[j];
    }
    __syncthreads();

    {
        float4 bv = *(const float4*)(b1 + tx * 4);
        float bbv[4] = {bv.x, bv.y, bv.z, bv.w};
        #pragma unroll
        for (int i = 0; i < 4; i++)
            #pragma unroll
            for (int j = 0; j < 4; j++)
                As[(tx * 4 + j) * 68 + ty * 4 + i] = fmaxf(acc[i][j] + bbv[j], 0.f);
    }
    #pragma unroll
    for (int r = 0; r < 2; r++) {
        int i = tid + r * 256;
        int k = i >> 3, nq = (i & 7) * 4;
        float4 v = *(const float4*)(W2 + (size_t)k * 32 + nq);
        Ws[k * 68 + nq]     = v.x; Ws[k * 68 + nq + 1] = v.y;
        Ws[k * 68 + nq + 2] = v.z; Ws[k * 68 + nq + 3] = v.w;
    }
    __syncthreads();

    // ---- y2 = relu(y1@W2+b2); out = y2@W3+b3 ----
    const int tx2 = tid & 15;
    const int ty2 = tid >> 4;
    float acc3[4][2] = {};
    #pragma unroll
    for (int kk = 0; kk < 64; kk++) {
        float4 a = *(const float4*)&As[kk * 68 + ty2 * 4];
        float b0v = Ws[kk * 68 + tx2 * 2];
        float b1v = Ws[kk * 68 + tx2 * 2 + 1];
        float am[4] = {a.x, a.y, a.z, a.w};
        #pragma unroll
        for (int i = 0; i < 4; i++) {
            acc3[i][0] += am[i] * b0v;
            acc3[i][1] += am[i] * b1v;
        }
    }
    float bb0 = b2[tx2 * 2], bb1 = b2[tx2 * 2 + 1];
    float w00 = W3[(tx2 * 2) * 2],     w01 = W3[(tx2 * 2) * 2 + 1];
    float w10 = W3[(tx2 * 2 + 1) * 2], w11 = W3[(tx2 * 2 + 1) * 2 + 1];

    #pragma unroll
    for (int i = 0; i < 4; i++) {
        float y0 = fmaxf(acc3[i][0] + bb0, 0.f);
        float y1v = fmaxf(acc3[i][1] + bb1, 0.f);
        float s0 = y0 * w00 + y1v * w10;
        float s1 = y0 * w01 + y1v * w11;
        #pragma unroll
        for (int o = 8; o > 0; o >>= 1) {
            s0 += __shfl_xor_sync(0xffffffffu, s0, o);
            s1 += __shfl_xor_sync(0xffffffffu, s1, o);
        }
        int gm = b0 + ty2 * 4 + i;
        if (tx2 == 0 && gm < nn) {
            out[gm * 2]     = s0 + b3[0];
            out[gm * 2 + 1] = s1 + b3[1];
        }
    }
}

// ---------------------------------------------------------------------------
extern "C" void kernel_launch(void* const* d_in, const int* in_sizes, int n_in,
                              void* d_out, int out_size)
{
    const float* x      = (const float*)d_in[0];
    const void*  esrc   = d_in[1];
    const void*  edst   = d_in[2];
    const float* ev     = (const float*)d_in[3];
    const float* Win    = (const float*)d_in[4];
    const float* bin    = (const float*)d_in[5];
    const float* thetas = (const float*)d_in[6];
    const float* Wb     = (const float*)d_in[7];
    const float* bWb    = (const float*)d_in[8];
    const float* Wx     = (const float*)d_in[9];
    const float* bWx    = (const float*)d_in[10];
    const float* vc     = (const float*)d_in[11];
    const float* W1     = (const float*)d_in[12];
    const float* b1     = (const float*)d_in[13];
    const float* W2     = (const float*)d_in[14];
    const float* b2     = (const float*)d_in[15];
    const float* W3     = (const float*)d_in[16];
    const float* b3     = (const float*)d_in[17];

    int n = in_sizes[0] / 128;
    int E = in_sizes[3];

    float *ph, *pT1, *pT2;
    cudaGetSymbolAddress((void**)&ph,  g_h);
    cudaGetSymbolAddress((void**)&pT1, g_T1);
    cudaGetSymbolAddress((void**)&pT2, g_T2);

    static int smem_set = 0;
    const int tail_smem = TAIL_SMEM_FLOATS * (int)sizeof(float);
    if (!smem_set) {
        cudaFuncSetAttribute(mega_tail,
                             cudaFuncAttributeMaxDynamicSharedMemorySize,
                             tail_smem);
        smem_set = 1;
    }

    prep_kernel<<<1, 32>>>(esrc, thetas);

    int GBt = (n + 127) / 128;
    int GA  = GBt / 2;
    int GB  = GBt - GA;
    int CB  = (E + 255) / 256;
    int nb  = (n + 1023) / 1024;

    // fat1: gemm rows [0, GA*128) || count histogram (+ flag zeroing)
    fat1<<<GA + CB, 256>>>(x, Win, bin, ph, n, edst, E, GA);

    // single-pass scan -> g_off
    scan_kernel<<<nb, 1024>>>(n);

    // fat2: gemm rows [GA*128, n) || scatter
    fat2<<<GB + CB, 256>>>(x, Win, bin, ph, n, esrc, edst, ev, E, GA, GB);

    // hops 1, 2 (2 rows/warp, float4 halves, unroll-8)
    int warps = (n + 1) / 2;
    int sb = (warps * 32 + 255) / 256;
    spmm_csr<<<sb, 256>>>(ph,  pT1, n);
    spmm_csr<<<sb, 256>>>(pT1, pT2, n);

    // fused hop-3 + poly + attention + MLP
    mega_tail<<<(n + 63) / 64, 256, tail_smem>>>(
        ph, pT1, pT2, Wx, bWx, Wb, bWb, vc,
        W1, b1, W2, b2, W3, b3, (float*)d_out, n);
}

// round 13
// speedup vs baseline: 1.1638x; 1.0597x over previous
#include <cuda_runtime.h>
#include <cstdint>

// ---------------------------------------------------------------------------
// NodeBernNet fixed shapes: N=100000, E=1600000, C_IN=128, C=64, F=2, K+1=4.
// R13: f32x2 packed FMA (fma.rn.f32x2) in all dense inner loops
// (input GEMM + tail xp/score/y1/y2). spmm untouched (memory-floor-bound).
// ---------------------------------------------------------------------------

#define NMAX 100000
#define EMAX 1600000
#define CDIM 64

__device__ __align__(256) float g_h [NMAX * CDIM];
__device__ __align__(256) float g_T1[NMAX * CDIM];
__device__ __align__(256) float g_T2[NMAX * CDIM];
// CSR scratch
__device__ int g_cnt[NMAX];                 // count adds, scatter subtracts -> 0
__device__ int g_off[NMAX + 1];
__device__ unsigned long long g_pack[128];  // lookback {flag<<32 | aggregate}
__device__ __align__(16) int2 g_csr[EMAX];  // {src, val bits}

__device__ float g_coef[8];   // thetas @ BCOEF, [F=2][K+1=4]
__device__ int   g_is64;

// ---------------------------------------------------------------------------
// Packed f32x2 helpers (Blackwell): one issue slot = two FMAs.
// ---------------------------------------------------------------------------
typedef unsigned long long u64;

__device__ __forceinline__ u64 bcast2(float x)
{
    u64 r;
    asm("mov.b64 %0, {%1, %1};" : "=l"(r) : "f"(x));
    return r;
}
__device__ __forceinline__ void fma2(u64& d, u64 a, u64 b)
{
    asm("fma.rn.f32x2 %0, %1, %2, %3;" : "=l"(d) : "l"(a), "l"(b), "l"(d));
}
__device__ __forceinline__ float2 unpack2(u64 v)
{
    float2 f;
    asm("mov.b64 {%0, %1}, %2;" : "=f"(f.x), "=f"(f.y) : "l"(v));
    return f;
}

// ---------------------------------------------------------------------------
__global__ void prep_kernel(const void* __restrict__ esrc,
                            const float* __restrict__ thetas)
{
    if (threadIdx.x == 0) {
        const int* w = (const int*)esrc;
        g_is64 = (w[1] == 0 && w[3] == 0 && w[5] == 0 && w[7] == 0) ? 1 : 0;
        const float B[4][4] = {
            {1.f, -3.f,  3.f, -1.f},
            {0.f,  3.f, -6.f,  3.f},
            {0.f,  0.f,  3.f, -3.f},
            {0.f,  0.f,  0.f,  1.f}};
        for (int f = 0; f < 2; f++)
            for (int k = 0; k < 4; k++) {
                float s = 0.f;
                for (int j = 0; j < 4; j++) s += thetas[f * 4 + j] * B[j][k];
                g_coef[f * 4 + k] = s;
            }
    }
}

// ---------------------------------------------------------------------------
// GEMM body: h = relu(x @ W_in + b_in), 128-row tile at m0. f32x2 inner loop.
// ---------------------------------------------------------------------------
__device__ __forceinline__ void gemm_body(const float* __restrict__ A,
                                          const float* __restrict__ W,
                                          const float* __restrict__ bias,
                                          float* __restrict__ C, int M, int m0)
{
    __shared__ float As[16][132];
    __shared__ float Bs[16][68];

    const int tid = threadIdx.x;
    const int tx = tid & 15;
    const int ty = tid >> 4;

    u64 accp[8][2] = {};   // (j0,j1) and (j2,j3) packed pairs per row i

    for (int k0 = 0; k0 < 128; k0 += 16) {
        #pragma unroll
        for (int r = 0; r < 2; r++) {
            int i = tid + r * 256;
            int row = i >> 2, kq = i & 3;
            int gm = m0 + row;
            float4 v = make_float4(0.f, 0.f, 0.f, 0.f);
            if (gm < M) v = *(const float4*)(A + (size_t)gm * 128 + k0 + kq * 4);
            As[kq * 4 + 0][row] = v.x;
            As[kq * 4 + 1][row] = v.y;
            As[kq * 4 + 2][row] = v.z;
            As[kq * 4 + 3][row] = v.w;
        }
        {
            int k = tid >> 4, nn = (tid & 15) * 4;
            float4 v = *(const float4*)(W + (size_t)(k0 + k) * 64 + nn);
            Bs[k][nn + 0] = v.x; Bs[k][nn + 1] = v.y;
            Bs[k][nn + 2] = v.z; Bs[k][nn + 3] = v.w;
        }
        __syncthreads();
        #pragma unroll
        for (int kk = 0; kk < 16; kk++) {
            float4 a0 = *(const float4*)&As[kk][ty * 8];
            float4 a1 = *(const float4*)&As[kk][ty * 8 + 4];
            u64 b01 = *(const u64*)&Bs[kk][tx * 4];
            u64 b23 = *(const u64*)&Bs[kk][tx * 4 + 2];
            float am[8] = {a0.x, a0.y, a0.z, a0.w, a1.x, a1.y, a1.z, a1.w};
            #pragma unroll
            for (int i = 0; i < 8; i++) {
                u64 ap = bcast2(am[i]);
                fma2(accp[i][0], ap, b01);
                fma2(accp[i][1], ap, b23);
            }
        }
        __syncthreads();
    }

    int nn = tx * 4;
    float4 bv = *(const float4*)(bias + nn);
    #pragma unroll
    for (int i = 0; i < 8; i++) {
        int gm = m0 + ty * 8 + i;
        if (gm >= M) continue;
        float2 p0 = unpack2(accp[i][0]);
        float2 p1 = unpack2(accp[i][1]);
        float4 o;
        o.x = fmaxf(p0.x + bv.x, 0.f);
        o.y = fmaxf(p0.y + bv.y, 0.f);
        o.z = fmaxf(p1.x + bv.z, 0.f);
        o.w = fmaxf(p1.y + bv.w, 0.f);
        *(float4*)(C + (size_t)gm * 64 + nn) = o;
    }
}

// ---------------------------------------------------------------------------
// fat1: blocks [0,GA) gemm rows [0,GA*128); blocks [GA,..) count histogram.
// ---------------------------------------------------------------------------
__global__ void fat1(const float* __restrict__ A,
                     const float* __restrict__ W,
                     const float* __restrict__ bias,
                     float* __restrict__ C, int M,
                     const void* __restrict__ edst, int E, int GA)
{
    if ((int)blockIdx.x >= GA) {
        if ((int)blockIdx.x == GA && threadIdx.x < 128)
            g_pack[threadIdx.x] = 0ULL;
        int e = (blockIdx.x - GA) * blockDim.x + threadIdx.x;
        if (e < E) {
            int dst = g_is64 ? (int)((const long long*)edst)[e]
                             : ((const int*)edst)[e];
            atomicAdd(&g_cnt[dst], 1);
        }
        return;
    }
    gemm_body(A, W, bias, C, M, blockIdx.x * 128);
}

// ---------------------------------------------------------------------------
// Single-pass scan with decoupled lookback.
// ---------------------------------------------------------------------------
__global__ void scan_kernel(int n)
{
    __shared__ int warp_sums[32];
    __shared__ int s_prefix;

    int t = threadIdx.x, bid = blockIdx.x;
    int i = bid * 1024 + t;
    int lane = t & 31, wid = t >> 5;

    int x = (i < n) ? g_cnt[i] : 0;
    #pragma unroll
    for (int o = 1; o < 32; o <<= 1) {
        int y = __shfl_up_sync(0xffffffffu, x, o);
        if (lane >= o) x += y;
    }
    if (lane == 31) warp_sums[wid] = x;
    __syncthreads();
    if (wid == 0) {
        int s = warp_sums[lane];
        #pragma unroll
        for (int o = 1; o < 32; o <<= 1) {
            int y = __shfl_up_sync(0xffffffffu, s, o);
            if (lane >= o) s += y;
        }
        warp_sums[lane] = s;
    }
    __syncthreads();
    int incl = x + (wid > 0 ? warp_sums[wid - 1] : 0);
    int aggregate = warp_sums[31];

    if (t == 0) {
        if (bid == 0) {
            *(volatile u64*)&g_pack[0] = (2ULL << 32) | (unsigned)aggregate;
            s_prefix = 0;
        } else {
            *(volatile u64*)&g_pack[bid] = (1ULL << 32) | (unsigned)aggregate;
            int sum = 0;
            for (int j = bid - 1; j >= 0; j--) {
                u64 p;
                do { p = *(volatile u64*)&g_pack[j]; }
                while ((p >> 32) == 0ULL);
                sum += (int)(unsigned)p;
                if ((p >> 32) == 2ULL) break;
            }
            *(volatile u64*)&g_pack[bid] =
                (2ULL << 32) | (unsigned)(sum + aggregate);
            s_prefix = sum;
        }
    }
    __syncthreads();
    if (i < n) g_off[i + 1] = s_prefix + incl;
    if (i == 0) g_off[0] = 0;
}

// ---------------------------------------------------------------------------
// fat2: blocks [0,GB) gemm rows from GA*128; rest scatter (self-zeroing cnt).
// ---------------------------------------------------------------------------
__global__ void fat2(const float* __restrict__ A,
                     const float* __restrict__ W,
                     const float* __restrict__ bias,
                     float* __restrict__ C, int M,
                     const void* __restrict__ esrc,
                     const void* __restrict__ edst,
                     const float* __restrict__ ev,
                     int E, int GA, int GB)
{
    if ((int)blockIdx.x >= GB) {
        int e = (blockIdx.x - GB) * 256 + threadIdx.x;
        if (e < E) {
            int src, dst;
            if (g_is64) {
                src = (int)((const long long*)esrc)[e];
                dst = (int)((const long long*)edst)[e];
            } else {
                src = ((const int*)esrc)[e];
                dst = ((const int*)edst)[e];
            }
            int old = atomicSub(&g_cnt[dst], 1);   // old in [1, cnt]
            g_csr[g_off[dst + 1] - old] = make_int2(src, __float_as_int(ev[e]));
        }
        return;
    }
    gemm_body(A, W, bias, C, M, (GA + blockIdx.x) * 128);
}

// ---------------------------------------------------------------------------
// Plain unroll-4 gather (proven) — used by the tail.
// ---------------------------------------------------------------------------
__device__ __forceinline__ float4 row_acc4(const float* __restrict__ hin,
                                           int s, int e, int lane16)
{
    float4 acc = make_float4(0.f, 0.f, 0.f, 0.f);
    int i = s;
    for (; i + 3 < e; i += 4) {
        int2 p0 = __ldg(&g_csr[i]);
        int2 p1 = __ldg(&g_csr[i + 1]);
        int2 p2 = __ldg(&g_csr[i + 2]);
        int2 p3 = __ldg(&g_csr[i + 3]);
        float4 h0 = *((const float4*)(hin + (size_t)p0.x * CDIM) + lane16);
        float4 h1 = *((const float4*)(hin + (size_t)p1.x * CDIM) + lane16);
        float4 h2 = *((const float4*)(hin + (size_t)p2.x * CDIM) + lane16);
        float4 h3 = *((const float4*)(hin + (size_t)p3.x * CDIM) + lane16);
        float v0 = __int_as_float(p0.y), v1 = __int_as_float(p1.y);
        float v2 = __int_as_float(p2.y), v3 = __int_as_float(p3.y);
        acc.x += v0 * h0.x + v1 * h1.x + v2 * h2.x + v3 * h3.x;
        acc.y += v0 * h0.y + v1 * h1.y + v2 * h2.y + v3 * h3.y;
        acc.z += v0 * h0.z + v1 * h1.z + v2 * h2.z + v3 * h3.z;
        acc.w += v0 * h0.w + v1 * h1.w + v2 * h2.w + v3 * h3.w;
    }
    for (; i < e; i++) {
        int2 p0 = __ldg(&g_csr[i]);
        float v0 = __int_as_float(p0.y);
        float4 h0 = *((const float4*)(hin + (size_t)p0.x * CDIM) + lane16);
        acc.x += v0 * h0.x; acc.y += v0 * h0.y;
        acc.z += v0 * h0.z; acc.w += v0 * h0.w;
    }
    return acc;
}

// ---------------------------------------------------------------------------
// spmm hop kernel: 2 rows/warp, float4 halves, flat unroll-8.
// ---------------------------------------------------------------------------
__global__ void spmm_csr(const float* __restrict__ hin,
                         float* __restrict__ hout, int n)
{
    int w = (blockIdx.x * blockDim.x + threadIdx.x) >> 5;
    int lane = threadIdx.x & 31;
    int r = w * 2 + (lane >> 4);
    if (r >= n) return;
    int lane16 = lane & 15;
    int s = g_off[r], e = g_off[r + 1];

    float4 acc = make_float4(0.f, 0.f, 0.f, 0.f);
    int i = s;
    for (; i + 7 < e; i += 8) {
        int2 p[8];
        #pragma unroll
        for (int u = 0; u < 8; u++) p[u] = __ldg(&g_csr[i + u]);
        float4 hv[8];
        #pragma unroll
        for (int u = 0; u < 8; u++)
            hv[u] = *((const float4*)(hin + (size_t)p[u].x * CDIM) + lane16);
        #pragma unroll
        for (int u = 0; u < 8; u++) {
            float v = __int_as_float(p[u].y);
            acc.x += v * hv[u].x;
            acc.y += v * hv[u].y;
            acc.z += v * hv[u].z;
            acc.w += v * hv[u].w;
        }
    }
    for (; i < e; i++) {
        int2 p0 = __ldg(&g_csr[i]);
        float v0 = __int_as_float(p0.y);
        float4 h0 = *((const float4*)(hin + (size_t)p0.x * CDIM) + lane16);
        acc.x += v0 * h0.x; acc.y += v0 * h0.y;
        acc.z += v0 * h0.z; acc.w += v0 * h0.w;
    }
    *((float4*)(hout + (size_t)r * CDIM) + lane16) = acc;
}

// ---------------------------------------------------------------------------
// Mega-tail: hop-3 gather + poly -> Ps; xp/score/y1/y2 with f32x2 FMA.
// 64 nodes per 256-thread block.
// ---------------------------------------------------------------------------
#define TAIL_SMEM_FLOATS (64*68 + 64*68 + 64*137 + 128 + 64 + 64)

__global__ void mega_tail(const float* __restrict__ h,
                          const float* __restrict__ t1,
                          const float* __restrict__ t2,
                          const float* __restrict__ Wx,
                          const float* __restrict__ bWx,
                          const float* __restrict__ Wb,
                          const float* __restrict__ bWb,
                          const float* __restrict__ vc,
                          const float* __restrict__ W1,
                          const float* __restrict__ b1,
                          const float* __restrict__ W2,
                          const float* __restrict__ b2,
                          const float* __restrict__ W3,
                          const float* __restrict__ b3,
                          float* __restrict__ out, int nn)
{
    extern __shared__ float sm[];
    float* As  = sm;                 // [k][m] 64x68
    float* Ws  = As + 64 * 68;       // [k][n] 64x68
    float* Ps  = Ws + 64 * 68;       // [c][row] 64x137 (poly, 128 rows)
    float* Ss  = Ps + 64 * 137;      // 128 scores
    float* Sa0 = Ss + 128;
    float* Sa1 = Sa0 + 64;

    const int tid = threadIdx.x;
    const int b0 = blockIdx.x * 64;
    const int tx = tid & 15;
    const int ty = tid >> 4;

    // ---- loaders: h rows -> As (transposed), Wx -> Ws ----
    #pragma unroll
    for (int r = 0; r < 4; r++) {
        int i = tid + r * 256;
        int m = i >> 4, q = i & 15;
        int gn = b0 + m;
        float4 v = make_float4(0.f, 0.f, 0.f, 0.f);
        if (gn < nn) v = *((const float4*)(h + (size_t)gn * 64) + q);
        As[(q * 4 + 0) * 68 + m] = v.x;
        As[(q * 4 + 1) * 68 + m] = v.y;
        As[(q * 4 + 2) * 68 + m] = v.z;
        As[(q * 4 + 3) * 68 + m] = v.w;
    }
    #pragma unroll
    for (int r = 0; r < 4; r++) {
        int i = tid + r * 256;
        int k = i >> 4, nq = (i & 15) * 4;
        float4 v = *(const float4*)(Wx + (size_t)k * 64 + nq);
        Ws[k * 68 + nq]     = v.x; Ws[k * 68 + nq + 1] = v.y;
        Ws[k * 68 + nq + 2] = v.z; Ws[k * 68 + nq + 3] = v.w;
    }

    // ---- stage A: hop-3 gather + poly, 2 rows per warp -> Ps ----
    {
        int wid = tid >> 5;
        int lane = tid & 31;
        int lane16 = lane & 15;
        float c00 = g_coef[0], c01 = g_coef[1], c02 = g_coef[2], c03 = g_coef[3];
        float c10 = g_coef[4], c11 = g_coef[5], c12 = g_coef[6], c13 = g_coef[7];
        #pragma unroll
        for (int it = 0; it < 4; it++) {
            int local = wid * 8 + it * 2 + (lane >> 4);
            int r = b0 + local;
            float4 p0 = make_float4(0.f, 0.f, 0.f, 0.f);
            float4 p1 = make_float4(0.f, 0.f, 0.f, 0.f);
            if (r < nn) {
                float4 d = row_acc4(t2, g_off[r], g_off[r + 1], lane16);
                float4 a = *((const float4*)(h  + (size_t)r * CDIM) + lane16);
                float4 b = *((const float4*)(t1 + (size_t)r * CDIM) + lane16);
                float4 c = *((const float4*)(t2 + (size_t)r * CDIM) + lane16);
                p0.x = c00*a.x + c01*b.x + c02*c.x + c03*d.x;
                p0.y = c00*a.y + c01*b.y + c02*c.y + c03*d.y;
                p0.z = c00*a.z + c01*b.z + c02*c.z + c03*d.z;
                p0.w = c00*a.w + c01*b.w + c02*c.w + c03*d.w;
                p1.x = c10*a.x + c11*b.x + c12*c.x + c13*d.x;
                p1.y = c10*a.y + c11*b.y + c12*c.y + c13*d.y;
                p1.z = c10*a.z + c11*b.z + c12*c.z + c13*d.z;
                p1.w = c10*a.w + c11*b.w + c12*c.w + c13*d.w;
            }
            int cb = lane16 * 4;
            int m2 = 2 * local;
            Ps[(cb + 0) * 137 + m2] = p0.x; Ps[(cb + 0) * 137 + m2 + 1] = p1.x;
            Ps[(cb + 1) * 137 + m2] = p0.y; Ps[(cb + 1) * 137 + m2 + 1] = p1.y;
            Ps[(cb + 2) * 137 + m2] = p0.z; Ps[(cb + 2) * 137 + m2 + 1] = p1.z;
            Ps[(cb + 3) * 137 + m2] = p0.w; Ps[(cb + 3) * 137 + m2 + 1] = p1.w;
        }
    }
    __syncthreads();

    // ---- stage 1: xp = h @ Wx + bWx (f32x2 pairs) ----
    u64 xpp[4][2] = {};
    #pragma unroll
    for (int kk = 0; kk < 64; kk++) {
        float4 a = *(const float4*)&As[kk * 68 + ty * 4];
        u64 b01 = *(const u64*)&Ws[kk * 68 + tx * 4];
        u64 b23 = *(const u64*)&Ws[kk * 68 + tx * 4 + 2];
        float am[4] = {a.x, a.y, a.z, a.w};
        #pragma unroll
        for (int i = 0; i < 4; i++) {
            u64 ap = bcast2(am[i]);
            fma2(xpp[i][0], ap, b01);
            fma2(xpp[i][1], ap, b23);
        }
    }
    float xp[4][4];
    {
        float4 bx = *(const float4*)(bWx + tx * 4);
        #pragma unroll
        for (int i = 0; i < 4; i++) {
            float2 p0 = unpack2(xpp[i][0]);
            float2 p1 = unpack2(xpp[i][1]);
            xp[i][0] = p0.x + bx.x; xp[i][1] = p0.y + bx.y;
            xp[i][2] = p1.x + bx.z; xp[i][3] = p1.y + bx.w;
        }
    }
    __syncthreads();

    // load Wb -> Ws
    #pragma unroll
    for (int r = 0; r < 4; r++) {
        int i = tid + r * 256;
        int k = i >> 4, nq = (i & 15) * 4;
        float4 v = *(const float4*)(Wb + (size_t)k * 64 + nq);
        Ws[k * 68 + nq]     = v.x; Ws[k * 68 + nq + 1] = v.y;
        Ws[k * 68 + nq + 2] = v.z; Ws[k * 68 + nq + 3] = v.w;
    }
    __syncthreads();

    // ---- stage 2: scores (f32x2 pairs) ----
    {
        u64 accp[8][2] = {};
        #pragma unroll
        for (int kk = 0; kk < 64; kk++) {
            u64 b01 = *(const u64*)&Ws[kk * 68 + tx * 4];
            u64 b23 = *(const u64*)&Ws[kk * 68 + tx * 4 + 2];
            const float* pr = &Ps[kk * 137 + ty * 8];
            #pragma unroll
            for (int i = 0; i < 8; i++) {
                u64 ap = bcast2(pr[i]);
                fma2(accp[i][0], ap, b01);
                fma2(accp[i][1], ap, b23);
            }
        }
        float4 bb = *(const float4*)(bWb + tx * 4);
        float4 vv = *(const float4*)(vc + tx * 4);
        #pragma unroll
        for (int i = 0; i < 8; i++) {
            int h2 = i >> 1;
            float2 p0 = unpack2(accp[i][0]);
            float2 p1 = unpack2(accp[i][1]);
            float part;
            part  = tanhf(p0.x + bb.x + xp[h2][0]) * vv.x;
            part += tanhf(p0.y + bb.y + xp[h2][1]) * vv.y;
            part += tanhf(p1.x + bb.z + xp[h2][2]) * vv.z;
            part += tanhf(p1.y + bb.w + xp[h2][3]) * vv.w;
            #pragma unroll
            for (int o = 8; o > 0; o >>= 1)
                part += __shfl_xor_sync(0xffffffffu, part, o);
            if (tx == 0) Ss[ty * 8 + i] = part;
        }
    }
    __syncthreads();

    // ---- softmax per node ----
    if (tid < 64) {
        float s0 = Ss[2 * tid], s1 = Ss[2 * tid + 1];
        float m = fmaxf(s0, s1);
        float e0 = expf(s0 - m), e1 = expf(s1 - m);
        float inv = 1.f / (e0 + e1);
        Sa0[tid] = e0 * inv;
        Sa1[tid] = e1 * inv;
    }
    __syncthreads();

    // ---- res -> As, W1 -> Ws ----
    #pragma unroll
    for (int r = 0; r < 16; r++) {
        int i = tid + r * 256;
        int c = i >> 6, m = i & 63;
        As[c * 68 + m] = Sa0[m] * Ps[c * 137 + 2 * m]
                       + Sa1[m] * Ps[c * 137 + 2 * m + 1];
    }
    #pragma unroll
    for (int r = 0; r < 4; r++) {
        int i = tid + r * 256;
        int k = i >> 4, nq = (i & 15) * 4;
        float4 v = *(const float4*)(W1 + (size_t)k * 64 + nq);
        Ws[k * 68 + nq]     = v.x; Ws[k * 68 + nq + 1] = v.y;
        Ws[k * 68 + nq + 2] = v.z; Ws[k * 68 + nq + 3] = v.w;
    }
    __syncthreads();

    // ---- y1 = relu(res @ W1 + b1) (f32x2 pairs) ----
    u64 y1p[4][2] = {};
    #pragma unroll
    for (int kk = 0; kk < 64; kk++) {
        float4 a = *(const float4*)&As[kk * 68 + ty * 4];
        u64 b01 = *(const u64*)&Ws[kk * 68 + tx * 4];
        u64 b23 = *(const u64*)&Ws[kk * 68 + tx * 4 + 2];
        float am[4] = {a.x, a.y, a.z, a.w};
        #pragma unroll
        for (int i = 0; i < 4; i++) {
            u64 ap = bcast2(am[i]);
            fma2(y1p[i][0], ap, b01);
            fma2(y1p[i][1], ap, b23);
        }
    }
    __syncthreads();

    {
        float4 bv = *(const float4*)(b1 + tx * 4);
        #pragma unroll
        for (int i = 0; i < 4; i++) {
            float2 p0 = unpack2(y1p[i][0]);
            float2 p1 = unpack2(y1p[i][1]);
            As[(tx * 4 + 0) * 68 + ty * 4 + i] = fmaxf(p0.x + bv.x, 0.f);
            As[(tx * 4 + 1) * 68 + ty * 4 + i] = fmaxf(p0.y + bv.y, 0.f);
            As[(tx * 4 + 2) * 68 + ty * 4 + i] = fmaxf(p1.x + bv.z, 0.f);
            As[(tx * 4 + 3) * 68 + ty * 4 + i] = fmaxf(p1.y + bv.w, 0.f);
        }
    }
    #pragma unroll
    for (int r = 0; r < 2; r++) {
        int i = tid + r * 256;
        int k = i >> 3, nq = (i & 7) * 4;
        float4 v = *(const float4*)(W2 + (size_t)k * 32 + nq);
        Ws[k * 68 + nq]     = v.x; Ws[k * 68 + nq + 1] = v.y;
        Ws[k * 68 + nq + 2] = v.z; Ws[k * 68 + nq + 3] = v.w;
    }
    __syncthreads();

    // ---- y2 = relu(y1@W2+b2); out = y2@W3+b3 (f32x2 pairs) ----
    const int tx2 = tid & 15;
    const int ty2 = tid >> 4;
    u64 acc3p[4] = {};
    #pragma unroll
    for (int kk = 0; kk < 64; kk++) {
        float4 a = *(const float4*)&As[kk * 68 + ty2 * 4];
        u64 bpair = *(const u64*)&Ws[kk * 68 + tx2 * 2];
        float am[4] = {a.x, a.y, a.z, a.w};
        #pragma unroll
        for (int i = 0; i < 4; i++) {
            u64 ap = bcast2(am[i]);
            fma2(acc3p[i], ap, bpair);
        }
    }
    float bb0 = b2[tx2 * 2], bb1 = b2[tx2 * 2 + 1];
    float w00 = W3[(tx2 * 2) * 2],     w01 = W3[(tx2 * 2) * 2 + 1];
    float w10 = W3[(tx2 * 2 + 1) * 2], w11 = W3[(tx2 * 2 + 1) * 2 + 1];

    #pragma unroll
    for (int i = 0; i < 4; i++) {
        float2 p = unpack2(acc3p[i]);
        float y0 = fmaxf(p.x + bb0, 0.f);
        float y1v = fmaxf(p.y + bb1, 0.f);
        float s0 = y0 * w00 + y1v * w10;
        float s1 = y0 * w01 + y1v * w11;
        #pragma unroll
        for (int o = 8; o > 0; o >>= 1) {
            s0 += __shfl_xor_sync(0xffffffffu, s0, o);
            s1 += __shfl_xor_sync(0xffffffffu, s1, o);
        }
        int gm = b0 + ty2 * 4 + i;
        if (tx2 == 0 && gm < nn) {
            out[gm * 2]     = s0 + b3[0];
            out[gm * 2 + 1] = s1 + b3[1];
        }
    }
}

// ---------------------------------------------------------------------------
extern "C" void kernel_launch(void* const* d_in, const int* in_sizes, int n_in,
                              void* d_out, int out_size)
{
    const float* x      = (const float*)d_in[0];
    const void*  esrc   = d_in[1];
    const void*  edst   = d_in[2];
    const float* ev     = (const float*)d_in[3];
    const float* Win    = (const float*)d_in[4];
    const float* bin    = (const float*)d_in[5];
    const float* thetas = (const float*)d_in[6];
    const float* Wb     = (const float*)d_in[7];
    const float* bWb    = (const float*)d_in[8];
    const float* Wx     = (const float*)d_in[9];
    const float* bWx    = (const float*)d_in[10];
    const float* vc     = (const float*)d_in[11];
    const float* W1     = (const float*)d_in[12];
    const float* b1     = (const float*)d_in[13];
    const float* W2     = (const float*)d_in[14];
    const float* b2     = (const float*)d_in[15];
    const float* W3     = (const float*)d_in[16];
    const float* b3     = (const float*)d_in[17];

    int n = in_sizes[0] / 128;
    int E = in_sizes[3];

    float *ph, *pT1, *pT2;
    cudaGetSymbolAddress((void**)&ph,  g_h);
    cudaGetSymbolAddress((void**)&pT1, g_T1);
    cudaGetSymbolAddress((void**)&pT2, g_T2);

    static int smem_set = 0;
    const int tail_smem = TAIL_SMEM_FLOATS * (int)sizeof(float);
    if (!smem_set) {
        cudaFuncSetAttribute(mega_tail,
                             cudaFuncAttributeMaxDynamicSharedMemorySize,
                             tail_smem);
        smem_set = 1;
    }

    prep_kernel<<<1, 32>>>(esrc, thetas);

    int GBt = (n + 127) / 128;
    int GA  = GBt / 2;
    int GB  = GBt - GA;
    int CB  = (E + 255) / 256;
    int nb  = (n + 1023) / 1024;

    // fat1: gemm rows [0, GA*128) || count histogram (+ flag zeroing)
    fat1<<<GA + CB, 256>>>(x, Win, bin, ph, n, edst, E, GA);

    // single-pass scan -> g_off
    scan_kernel<<<nb, 1024>>>(n);

    // fat2: gemm rows [GA*128, n) || scatter
    fat2<<<GB + CB, 256>>>(x, Win, bin, ph, n, esrc, edst, ev, E, GA, GB);

    // hops 1, 2
    int warps = (n + 1) / 2;
    int sb = (warps * 32 + 255) / 256;
    spmm_csr<<<sb, 256>>>(ph,  pT1, n);
    spmm_csr<<<sb, 256>>>(pT1, pT2, n);

    // fused hop-3 + poly + attention + MLP
    mega_tail<<<(n + 63) / 64, 256, tail_smem>>>(
        ph, pT1, pT2, Wx, bWx, Wb, bWb, vc,
        W1, b1, W2, b2, W3, b3, (float*)d_out, n);
}